// round 9
// baseline (speedup 1.0000x reference)
#include <cuda_runtime.h>
#include <math.h>

#define NTOK 8192
#define NEXP 64

typedef unsigned long long u64;

// Scratch (device globals: allocation-free)
__device__ float g_h[NTOK * 4096];
__device__ int   g_idx_up[NTOK * 2];
__device__ float g_prob_up[NTOK * 2];
__device__ int   g_idx_dn[NTOK * 2];
__device__ float g_prob_dn[NTOK * 2];
__device__ int   g_cnt[128];
__device__ int   g_off[128];
__device__ int   g_poff[132];
__device__ int   g_tileE[2 * 1152];
__device__ int   g_perm[2 * NTOK];

__device__ __forceinline__ void ffma2(u64& d, u64 a, u64 b) {
    asm("fma.rn.f32x2 %0, %1, %2, %0;" : "+l"(d) : "l"(a), "l"(b));
}
__device__ __forceinline__ u64 dup2(float f) {
    u64 r; asm("mov.b64 %0, {%1, %1};" : "=l"(r) : "f"(f)); return r;
}
__device__ __forceinline__ float2 unpk(u64 a) {
    float2 f; asm("mov.b64 {%0, %1}, %2;" : "=f"(f.x), "=f"(f.y) : "l"(a)); return f;
}
__device__ __forceinline__ float hadd(u64 a) {
    float2 f = unpk(a); return f.x + f.y;
}
__device__ __forceinline__ float gelu_f(float y) {
    return 0.5f * y * (1.f + erff(y * 0.70710678118654752f));
}

// ---------------------------------------------------------------------------
// Router (unchanged): logits = x @ W^T, fused top-2 + softmax.
// ---------------------------------------------------------------------------
template <int D>
__global__ void __launch_bounds__(256, 2)
router_kernel(const float* __restrict__ x, const float* __restrict__ W,
              int* __restrict__ idx, float* __restrict__ prob)
{
    __shared__ float xs[64][36];
    __shared__ float ws[64][36];
    __shared__ float ls[64][65];

    const int tid  = threadIdx.x;
    const int tok0 = blockIdx.x * 64;
    const int tr   = (tid >> 4) * 4;
    const int eb   = tid & 15;

    u64 acc[4][4];
#pragma unroll
    for (int i = 0; i < 4; i++)
#pragma unroll
        for (int j = 0; j < 4; j++) acc[i][j] = 0ull;

    for (int d0 = 0; d0 < D; d0 += 32) {
        {
            int l = tid;
            int r = l >> 3, c4 = (l & 7) * 4;
            *(float4*)&xs[r][c4] = *(const float4*)&x[(tok0 + r) * D + d0 + c4];
            *(float4*)&ws[r][c4] = *(const float4*)&W[r * D + d0 + c4];
            l += 256;
            r = l >> 3; c4 = (l & 7) * 4;
            *(float4*)&xs[r][c4] = *(const float4*)&x[(tok0 + r) * D + d0 + c4];
            *(float4*)&ws[r][c4] = *(const float4*)&W[r * D + d0 + c4];
        }
        __syncthreads();
#pragma unroll
        for (int d4 = 0; d4 < 32; d4 += 4) {
            ulonglong2 xa[4], wb[4];
#pragma unroll
            for (int i = 0; i < 4; i++)
                xa[i] = *(const ulonglong2*)&xs[tr + i][d4];
#pragma unroll
            for (int j = 0; j < 4; j++)
                wb[j] = *(const ulonglong2*)&ws[eb + 16 * j][d4];
#pragma unroll
            for (int i = 0; i < 4; i++)
#pragma unroll
                for (int j = 0; j < 4; j++) {
                    ffma2(acc[i][j], xa[i].x, wb[j].x);
                    ffma2(acc[i][j], xa[i].y, wb[j].y);
                }
        }
        __syncthreads();
    }

#pragma unroll
    for (int i = 0; i < 4; i++)
#pragma unroll
        for (int j = 0; j < 4; j++)
            ls[tr + i][eb + 16 * j] = hadd(acc[i][j]);
    __syncthreads();

    if (tid < 64) {
        float v0 = -INFINITY, v1 = -INFINITY;
        int i0 = 0, i1 = 0;
        for (int e = 0; e < NEXP; e++) {
            float v = ls[tid][e];
            if (v > v0) { v1 = v0; i1 = i0; v0 = v; i0 = e; }
            else if (v > v1) { v1 = v; i1 = e; }
        }
        float e1 = expf(v1 - v0);
        float p0 = 1.f / (1.f + e1);
        int t = tok0 + tid;
        idx[t * 2 + 0]  = i0;
        idx[t * 2 + 1]  = i1;
        prob[t * 2 + 0] = p0;
        prob[t * 2 + 1] = 1.f - p0;
    }
}

// ---------------------------------------------------------------------------
// Deterministic counting sort of (token,k) slots by expert.
// ---------------------------------------------------------------------------
__global__ void zero_kernel(int* cnt) { cnt[threadIdx.x] = 0; }

__global__ void count_kernel(const int* __restrict__ idx, int* cnt) {
    int t = blockIdx.x * 256 + threadIdx.x;
    atomicAdd(&cnt[idx[2 * t]], 1);
    atomicAdd(&cnt[64 + idx[2 * t + 1]], 1);
}

__global__ void scan_kernel(const int* __restrict__ cnt, int* off, int* poff,
                            int* tileE) {
    if (threadIdx.x == 0) {
        for (int k = 0; k < 2; k++) {
            int s = 0, p = 0;
            for (int e = 0; e < 64; e++) {
                off[k * 64 + e]  = s; s += cnt[k * 64 + e];
                poff[k * 65 + e] = p;
                int nt = (cnt[k * 64 + e] + 7) >> 3;
                for (int q = 0; q < nt; q++) tileE[k * 1152 + p + q] = e;
                p += nt;
            }
            poff[k * 65 + 64] = p;
            for (int q = p; q < 1152; q++) tileE[k * 1152 + q] = -1;
        }
    }
}

// one block per (k,expert); stable in token order -> deterministic
__global__ void scatter_kernel(const int* __restrict__ idx,
                               const int* __restrict__ off,
                               int* __restrict__ perm) {
    int k = blockIdx.x >> 6, e = blockIdx.x & 63;
    int base = off[k * 64 + e];
    __shared__ int warp_tot[8];
    __shared__ int carry;
    if (threadIdx.x == 0) carry = 0;
    __syncthreads();
    for (int t0 = 0; t0 < NTOK; t0 += 256) {
        int t = t0 + threadIdx.x;
        bool m = (idx[2 * t + k] == e);
        unsigned bal = __ballot_sync(0xffffffffu, m);
        int lane = threadIdx.x & 31, wid = threadIdx.x >> 5;
        int wpre = __popc(bal & ((1u << lane) - 1));
        if (lane == 0) warp_tot[wid] = __popc(bal);
        __syncthreads();
        int wbase = 0;
#pragma unroll
        for (int w = 0; w < 8; w++) if (w < wid) wbase += warp_tot[w];
        int tot = 0;
#pragma unroll
        for (int w = 0; w < 8; w++) tot += warp_tot[w];
        if (m) perm[k * NTOK + base + carry + wbase + wpre] = t;
        __syncthreads();
        if (threadIdx.x == 0) carry += tot;
        __syncthreads();
    }
}

// ---------------------------------------------------------------------------
// UP expert-grouped: 8 same-expert slots per CTA.
//   T[t] = pk * A_e @ X[t] ([64,32]@[32,32]),  Y[t] = T[t] @ B_e^T ([64,64])
// KP=0: h = Y;  KP=1: h = gelu(scale*(h + Y) + bias)
// smem floats: AsT[32][66] | BsT[32][66] | Xsn[32][264] | Ts[8][64][34]
// ---------------------------------------------------------------------------
#define UOFF_A 0
#define UOFF_B 2112
#define UOFF_X 4224
#define UOFF_T 12672
#define UP_SMEM_BYTES (30080 * 4)

template <int KP>
__global__ void __launch_bounds__(256, 1)
up_gemm(const float* __restrict__ x, const float* __restrict__ A,
        const float* __restrict__ Bw, const float* __restrict__ scale,
        const float* __restrict__ bias, const float* __restrict__ prob,
        const int* __restrict__ perm, const int* __restrict__ off,
        const int* __restrict__ poff, const int* __restrict__ cnt,
        const int* __restrict__ tileE, float* __restrict__ h)
{
    extern __shared__ float sm[];
    __shared__ int sh_e, sh_t[8], sh_v[8];
    __shared__ float sh_pk[8];
    const int tid = threadIdx.x;

    if (tid == 0) {
        int b = blockIdx.x;
        int e = tileE[KP * 1152 + b];
        sh_e = e;
        if (e >= 0) {
            int n = cnt[KP * 64 + e], base = off[KP * 64 + e];
            int l0 = (b - poff[KP * 65 + e]) * 8;
            for (int s = 0; s < 8; s++) {
                int li = l0 + s;
                if (li < n) {
                    int t = perm[KP * NTOK + base + li];
                    sh_t[s] = t; sh_v[s] = 1; sh_pk[s] = prob[2 * t + KP];
                } else { sh_t[s] = 0; sh_v[s] = 0; sh_pk[s] = 0.f; }
            }
        }
    }
    __syncthreads();
    if (sh_e < 0) return;
    const int e = sh_e;

    {   // A_e,B_e transposed: AsT[i][o], BsT[j][p]; X: Xsn[i][32s+j]
        const float4* A4 = (const float4*)(A + e * 2048);
        const float4* B4 = (const float4*)(Bw + e * 2048);
#pragma unroll
        for (int l = tid; l < 512; l += 256) {
            int o = l >> 3, c4 = (l & 7) * 4;
            float4 va = A4[l], vb = B4[l];
            sm[UOFF_A + (c4 + 0) * 66 + o] = va.x;
            sm[UOFF_A + (c4 + 1) * 66 + o] = va.y;
            sm[UOFF_A + (c4 + 2) * 66 + o] = va.z;
            sm[UOFF_A + (c4 + 3) * 66 + o] = va.w;
            sm[UOFF_B + (c4 + 0) * 66 + o] = vb.x;
            sm[UOFF_B + (c4 + 1) * 66 + o] = vb.y;
            sm[UOFF_B + (c4 + 2) * 66 + o] = vb.z;
            sm[UOFF_B + (c4 + 3) * 66 + o] = vb.w;
        }
        int i = tid >> 3, j4 = (tid & 7) * 4;
#pragma unroll 1
        for (int s = 0; s < 8; s++)
            *(float4*)&sm[UOFF_X + i * 264 + s * 32 + j4] =
                *(const float4*)&x[sh_t[s] * 1024 + i * 32 + j4];
    }
    __syncthreads();

    {   // GEMM1: thread = (og: o-pairs 8og+2q, ng = j), all 8 tokens
        const int og = tid >> 5, ng = tid & 31;
        u64 acc[4][8];
#pragma unroll
        for (int q = 0; q < 4; q++)
#pragma unroll
            for (int nn = 0; nn < 8; nn++) acc[q][nn] = 0ull;
#pragma unroll 8
        for (int i = 0; i < 32; i++) {
            u64 a[4];
#pragma unroll
            for (int q = 0; q < 4; q++)
                a[q] = *(const u64*)&sm[UOFF_A + i * 66 + 8 * og + 2 * q];
            u64 xv[8];
#pragma unroll
            for (int nn = 0; nn < 8; nn++)
                xv[nn] = dup2(sm[UOFF_X + i * 264 + 32 * nn + ng]);
#pragma unroll
            for (int q = 0; q < 4; q++)
#pragma unroll
                for (int nn = 0; nn < 8; nn++)
                    ffma2(acc[q][nn], a[q], xv[nn]);
        }
#pragma unroll
        for (int q = 0; q < 4; q++)
#pragma unroll
            for (int nn = 0; nn < 8; nn++) {
                float2 f = unpk(acc[q][nn]);
                float pk = sh_pk[nn];
                int o = 8 * og + 2 * q;
                sm[UOFF_T + nn * 2176 + o * 34 + ng]       = f.x * pk;
                sm[UOFF_T + nn * 2176 + (o + 1) * 34 + ng] = f.y * pk;
            }
    }
    __syncthreads();

    {   // GEMM2: Y[t][o][p] = sum_j T[t][o][j] B[p][j], p-pairs packed
        const int og2 = (tid >> 3) & 15, ppg = tid & 7, tg = tid >> 7;
        const float s0 = scale[0];
#pragma unroll 1
        for (int th = 0; th < 2; th++) {
            u64 acc[4][4][2];
#pragma unroll
            for (int oo = 0; oo < 4; oo++)
#pragma unroll
                for (int qq = 0; qq < 4; qq++) { acc[oo][qq][0] = 0ull; acc[oo][qq][1] = 0ull; }
#pragma unroll 8
            for (int j = 0; j < 32; j++) {
                u64 bv[4];
#pragma unroll
                for (int qq = 0; qq < 4; qq++)
                    bv[qq] = *(const u64*)&sm[UOFF_B + j * 66 + 2 * (ppg + 8 * qq)];
                u64 tv[4][2];
#pragma unroll
                for (int oo = 0; oo < 4; oo++)
#pragma unroll
                    for (int tt = 0; tt < 2; tt++)
                        tv[oo][tt] = dup2(sm[UOFF_T + (th * 4 + tg * 2 + tt) * 2176 +
                                             (og2 * 4 + oo) * 34 + j]);
#pragma unroll
                for (int oo = 0; oo < 4; oo++)
#pragma unroll
                    for (int qq = 0; qq < 4; qq++)
#pragma unroll
                        for (int tt = 0; tt < 2; tt++)
                            ffma2(acc[oo][qq][tt], tv[oo][tt], bv[qq]);
            }
#pragma unroll
            for (int oo = 0; oo < 4; oo++)
#pragma unroll
                for (int qq = 0; qq < 4; qq++)
#pragma unroll
                    for (int tt = 0; tt < 2; tt++) {
                        int s = th * 4 + tg * 2 + tt;
                        if (sh_v[s]) {
                            float2 f = unpk(acc[oo][qq][tt]);
                            int o = og2 * 4 + oo, p = 2 * (ppg + 8 * qq);
                            float* dst = h + sh_t[s] * 4096 + o * 64 + p;
                            if (KP == 0) {
                                *(float2*)dst = f;
                            } else {
                                float2 cur = *(const float2*)dst;
                                float y0 = (cur.x + f.x) * s0 + bias[o * 64 + p];
                                float y1 = (cur.y + f.y) * s0 + bias[o * 64 + p + 1];
                                *(float2*)dst = make_float2(gelu_f(y0), gelu_f(y1));
                            }
                        }
                    }
        }
    }
}

// ---------------------------------------------------------------------------
// DOWN expert-grouped: 8 same-expert slots per CTA.
//   T[t] = pk * A_e @ X[t] ([32,64]@[64,64]),  Y[t] = T[t] @ B_e^T ([32,32])
// X streamed in 4 slabs of 16 rows.
// smem floats: AsT[64][34] | BsT[64][34] | Xsn[16][520] | Ts[8][32][67]
// ---------------------------------------------------------------------------
#define DOFF_A 0
#define DOFF_B 2176
#define DOFF_X 4352
#define DOFF_T 12672
#define DN_SMEM_BYTES (29824 * 4)

template <int KP>
__global__ void __launch_bounds__(256, 1)
down_gemm(const float* __restrict__ hbuf, const float* __restrict__ A,
          const float* __restrict__ Bw, const float* __restrict__ scale,
          const float* __restrict__ bias, const float* __restrict__ prob,
          const int* __restrict__ perm, const int* __restrict__ off,
          const int* __restrict__ poff, const int* __restrict__ cnt,
          const int* __restrict__ tileE, float* __restrict__ out)
{
    extern __shared__ float sm[];
    __shared__ int sh_e, sh_t[8], sh_v[8];
    __shared__ float sh_pk[8];
    const int tid = threadIdx.x;

    if (tid == 0) {
        int b = blockIdx.x;
        int e = tileE[KP * 1152 + b];
        sh_e = e;
        if (e >= 0) {
            int n = cnt[KP * 64 + e], base = off[KP * 64 + e];
            int l0 = (b - poff[KP * 65 + e]) * 8;
            for (int s = 0; s < 8; s++) {
                int li = l0 + s;
                if (li < n) {
                    int t = perm[KP * NTOK + base + li];
                    sh_t[s] = t; sh_v[s] = 1; sh_pk[s] = prob[2 * t + KP];
                } else { sh_t[s] = 0; sh_v[s] = 0; sh_pk[s] = 0.f; }
            }
        }
    }
    __syncthreads();
    if (sh_e < 0) return;
    const int e = sh_e;

    {   // A_e [32][64] -> AsT[i][o]; B_e [32][64] -> BsT[j][p]
        const float4* A4 = (const float4*)(A + e * 2048);
        const float4* B4 = (const float4*)(Bw + e * 2048);
#pragma unroll
        for (int l = tid; l < 512; l += 256) {
            int o = l >> 4, c4 = (l & 15) * 4;
            float4 va = A4[l], vb = B4[l];
            sm[DOFF_A + (c4 + 0) * 34 + o] = va.x;
            sm[DOFF_A + (c4 + 1) * 34 + o] = va.y;
            sm[DOFF_A + (c4 + 2) * 34 + o] = va.z;
            sm[DOFF_A + (c4 + 3) * 34 + o] = va.w;
            sm[DOFF_B + (c4 + 0) * 34 + o] = vb.x;
            sm[DOFF_B + (c4 + 1) * 34 + o] = vb.y;
            sm[DOFF_B + (c4 + 2) * 34 + o] = vb.z;
            sm[DOFF_B + (c4 + 3) * 34 + o] = vb.w;
        }
    }

    {   // GEMM1 with X streamed in 4 slabs of 16 i-rows
        const int og = tid >> 6, ng = tid & 63;
        u64 acc[4][8];
#pragma unroll
        for (int q = 0; q < 4; q++)
#pragma unroll
            for (int nn = 0; nn < 8; nn++) acc[q][nn] = 0ull;

        const int xi = tid >> 4, xj4 = (tid & 15) * 4;
#pragma unroll 1
        for (int slab = 0; slab < 4; slab++) {
            __syncthreads();
#pragma unroll 1
            for (int s = 0; s < 8; s++)
                *(float4*)&sm[DOFF_X + xi * 520 + s * 64 + xj4] =
                    *(const float4*)&hbuf[sh_t[s] * 4096 + (slab * 16 + xi) * 64 + xj4];
            __syncthreads();
#pragma unroll 8
            for (int i = 0; i < 16; i++) {
                int gi = slab * 16 + i;
                u64 a[4];
#pragma unroll
                for (int q = 0; q < 4; q++)
                    a[q] = *(const u64*)&sm[DOFF_A + gi * 34 + 8 * og + 2 * q];
                u64 xv[8];
#pragma unroll
                for (int nn = 0; nn < 8; nn++)
                    xv[nn] = dup2(sm[DOFF_X + i * 520 + 64 * nn + ng]);
#pragma unroll
                for (int q = 0; q < 4; q++)
#pragma unroll
                    for (int nn = 0; nn < 8; nn++)
                        ffma2(acc[q][nn], a[q], xv[nn]);
            }
        }
#pragma unroll
        for (int q = 0; q < 4; q++)
#pragma unroll
            for (int nn = 0; nn < 8; nn++) {
                float2 f = unpk(acc[q][nn]);
                float pk = sh_pk[nn];
                int o = 8 * og + 2 * q;
                sm[DOFF_T + nn * 2144 + o * 67 + ng]       = f.x * pk;
                sm[DOFF_T + nn * 2144 + (o + 1) * 67 + ng] = f.y * pk;
            }
    }
    __syncthreads();

    {   // GEMM2: Y[t][o][p], p-pairs packed
        const int og3 = (tid >> 3) & 7, ppg = tid & 7, tg = tid >> 6;
        const float s0 = scale[0];
        u64 acc[4][2][2];
#pragma unroll
        for (int oo = 0; oo < 4; oo++)
#pragma unroll
            for (int qq = 0; qq < 2; qq++) { acc[oo][qq][0] = 0ull; acc[oo][qq][1] = 0ull; }
#pragma unroll 8
        for (int j = 0; j < 64; j++) {
            u64 bv[2];
#pragma unroll
            for (int qq = 0; qq < 2; qq++)
                bv[qq] = *(const u64*)&sm[DOFF_B + j * 34 + 2 * (ppg + 8 * qq)];
            u64 tv[4][2];
#pragma unroll
            for (int oo = 0; oo < 4; oo++)
#pragma unroll
                for (int tt = 0; tt < 2; tt++)
                    tv[oo][tt] = dup2(sm[DOFF_T + (tg * 2 + tt) * 2144 +
                                         (og3 * 4 + oo) * 67 + j]);
#pragma unroll
            for (int oo = 0; oo < 4; oo++)
#pragma unroll
                for (int qq = 0; qq < 2; qq++)
#pragma unroll
                    for (int tt = 0; tt < 2; tt++)
                        ffma2(acc[oo][qq][tt], tv[oo][tt], bv[qq]);
        }
#pragma unroll
        for (int oo = 0; oo < 4; oo++)
#pragma unroll
            for (int qq = 0; qq < 2; qq++)
#pragma unroll
                for (int tt = 0; tt < 2; tt++) {
                    int s = tg * 2 + tt;
                    if (sh_v[s]) {
                        float2 f = unpk(acc[oo][qq][tt]);
                        int o = og3 * 4 + oo, p = 2 * (ppg + 8 * qq);
                        float* dst = out + sh_t[s] * 1024 + o * 32 + p;
                        if (KP == 0) {
                            *(float2*)dst = f;
                        } else {
                            float2 cur = *(const float2*)dst;
                            *(float2*)dst = make_float2(
                                (cur.x + f.x) * s0 + bias[o * 32 + p],
                                (cur.y + f.y) * s0 + bias[o * 32 + p + 1]);
                        }
                    }
                }
    }
}

// ---------------------------------------------------------------------------
extern "C" void kernel_launch(void* const* d_in, const int* in_sizes, int n_in,
                              void* d_out, int out_size)
{
    const float* x          = (const float*)d_in[0];
    const float* W_up       = (const float*)d_in[1];
    const float* A_up       = (const float*)d_in[2];
    const float* B_up       = (const float*)d_in[3];
    const float* scale_up   = (const float*)d_in[4];
    const float* bias_up    = (const float*)d_in[5];
    const float* W_down     = (const float*)d_in[6];
    const float* A_down     = (const float*)d_in[7];
    const float* B_down     = (const float*)d_in[8];
    const float* scale_down = (const float*)d_in[9];
    const float* bias_down  = (const float*)d_in[10];
    float* out = (float*)d_out;

    float *h, *pu, *pd;
    int *iu, *idn, *cnt, *off, *poff, *tileE, *perm;
    cudaGetSymbolAddress((void**)&h,     g_h);
    cudaGetSymbolAddress((void**)&iu,    g_idx_up);
    cudaGetSymbolAddress((void**)&pu,    g_prob_up);
    cudaGetSymbolAddress((void**)&idn,   g_idx_dn);
    cudaGetSymbolAddress((void**)&pd,    g_prob_dn);
    cudaGetSymbolAddress((void**)&cnt,   g_cnt);
    cudaGetSymbolAddress((void**)&off,   g_off);
    cudaGetSymbolAddress((void**)&poff,  g_poff);
    cudaGetSymbolAddress((void**)&tileE, g_tileE);
    cudaGetSymbolAddress((void**)&perm,  g_perm);

    cudaFuncSetAttribute(up_gemm<0>,   cudaFuncAttributeMaxDynamicSharedMemorySize, UP_SMEM_BYTES);
    cudaFuncSetAttribute(up_gemm<1>,   cudaFuncAttributeMaxDynamicSharedMemorySize, UP_SMEM_BYTES);
    cudaFuncSetAttribute(down_gemm<0>, cudaFuncAttributeMaxDynamicSharedMemorySize, DN_SMEM_BYTES);
    cudaFuncSetAttribute(down_gemm<1>, cudaFuncAttributeMaxDynamicSharedMemorySize, DN_SMEM_BYTES);

    const int GRID = 1088;  // >= max tiles per pass (1024 + 64 padding)

    // up path
    router_kernel<1024><<<NTOK / 64, 256>>>(x, W_up, iu, pu);
    zero_kernel<<<1, 128>>>(cnt);
    count_kernel<<<NTOK / 256, 256>>>(iu, cnt);
    scan_kernel<<<1, 32>>>(cnt, off, poff, tileE);
    scatter_kernel<<<128, 256>>>(iu, off, perm);
    up_gemm<0><<<GRID, 256, UP_SMEM_BYTES>>>(x, A_up, B_up, scale_up, bias_up,
                                             pu, perm, off, poff, cnt, tileE, h);
    up_gemm<1><<<GRID, 256, UP_SMEM_BYTES>>>(x, A_up, B_up, scale_up, bias_up,
                                             pu, perm, off, poff, cnt, tileE, h);

    // down path
    router_kernel<4096><<<NTOK / 64, 256>>>(h, W_down, idn, pd);
    zero_kernel<<<1, 128>>>(cnt);
    count_kernel<<<NTOK / 256, 256>>>(idn, cnt);
    scan_kernel<<<1, 32>>>(cnt, off, poff, tileE);
    scatter_kernel<<<128, 256>>>(idn, off, perm);
    down_gemm<0><<<GRID, 256, DN_SMEM_BYTES>>>(h, A_down, B_down, scale_down, bias_down,
                                               pd, perm, off, poff, cnt, tileE, out);
    down_gemm<1><<<GRID, 256, DN_SMEM_BYTES>>>(h, A_down, B_down, scale_down, bias_down,
                                               pd, perm, off, poff, cnt, tileE, out);
}

// round 10
// speedup vs baseline: 1.4791x; 1.4791x over previous
#include <cuda_runtime.h>
#include <math.h>

#define NTOK 8192
#define NEXP 64

typedef unsigned long long u64;

// Scratch (device globals: allocation-free)
__device__ float g_h[NTOK * 4096];
__device__ int   g_idx_up[NTOK * 2];
__device__ float g_prob_up[NTOK * 2];
__device__ int   g_idx_dn[NTOK * 2];
__device__ float g_prob_dn[NTOK * 2];
__device__ int   g_cnt[128];
__device__ int   g_off[128];
__device__ int   g_poff[132];
__device__ int   g_tileE[2 * 1152];
__device__ int   g_perm[2 * NTOK];

__device__ __forceinline__ void ffma2(u64& d, u64 a, u64 b) {
    asm("fma.rn.f32x2 %0, %1, %2, %0;" : "+l"(d) : "l"(a), "l"(b));
}
__device__ __forceinline__ u64 dup2(float f) {
    u64 r; asm("mov.b64 %0, {%1, %1};" : "=l"(r) : "f"(f)); return r;
}
__device__ __forceinline__ float2 unpk(u64 a) {
    float2 f; asm("mov.b64 {%0, %1}, %2;" : "=f"(f.x), "=f"(f.y) : "l"(a)); return f;
}
__device__ __forceinline__ float hadd(u64 a) {
    float2 f = unpk(a); return f.x + f.y;
}
__device__ __forceinline__ float gelu_f(float y) {
    return 0.5f * y * (1.f + erff(y * 0.70710678118654752f));
}

// ---------------------------------------------------------------------------
// Router (unchanged): logits = x @ W^T, fused top-2 + softmax.
// ---------------------------------------------------------------------------
template <int D>
__global__ void __launch_bounds__(256, 2)
router_kernel(const float* __restrict__ x, const float* __restrict__ W,
              int* __restrict__ idx, float* __restrict__ prob)
{
    __shared__ float xs[64][36];
    __shared__ float ws[64][36];
    __shared__ float ls[64][65];

    const int tid  = threadIdx.x;
    const int tok0 = blockIdx.x * 64;
    const int tr   = (tid >> 4) * 4;
    const int eb   = tid & 15;

    u64 acc[4][4];
#pragma unroll
    for (int i = 0; i < 4; i++)
#pragma unroll
        for (int j = 0; j < 4; j++) acc[i][j] = 0ull;

    for (int d0 = 0; d0 < D; d0 += 32) {
        {
            int l = tid;
            int r = l >> 3, c4 = (l & 7) * 4;
            *(float4*)&xs[r][c4] = *(const float4*)&x[(tok0 + r) * D + d0 + c4];
            *(float4*)&ws[r][c4] = *(const float4*)&W[r * D + d0 + c4];
            l += 256;
            r = l >> 3; c4 = (l & 7) * 4;
            *(float4*)&xs[r][c4] = *(const float4*)&x[(tok0 + r) * D + d0 + c4];
            *(float4*)&ws[r][c4] = *(const float4*)&W[r * D + d0 + c4];
        }
        __syncthreads();
#pragma unroll
        for (int d4 = 0; d4 < 32; d4 += 4) {
            ulonglong2 xa[4], wb[4];
#pragma unroll
            for (int i = 0; i < 4; i++)
                xa[i] = *(const ulonglong2*)&xs[tr + i][d4];
#pragma unroll
            for (int j = 0; j < 4; j++)
                wb[j] = *(const ulonglong2*)&ws[eb + 16 * j][d4];
#pragma unroll
            for (int i = 0; i < 4; i++)
#pragma unroll
                for (int j = 0; j < 4; j++) {
                    ffma2(acc[i][j], xa[i].x, wb[j].x);
                    ffma2(acc[i][j], xa[i].y, wb[j].y);
                }
        }
        __syncthreads();
    }

#pragma unroll
    for (int i = 0; i < 4; i++)
#pragma unroll
        for (int j = 0; j < 4; j++)
            ls[tr + i][eb + 16 * j] = hadd(acc[i][j]);
    __syncthreads();

    if (tid < 64) {
        float v0 = -INFINITY, v1 = -INFINITY;
        int i0 = 0, i1 = 0;
        for (int e = 0; e < NEXP; e++) {
            float v = ls[tid][e];
            if (v > v0) { v1 = v0; i1 = i0; v0 = v; i0 = e; }
            else if (v > v1) { v1 = v; i1 = e; }
        }
        float e1 = expf(v1 - v0);
        float p0 = 1.f / (1.f + e1);
        int t = tok0 + tid;
        idx[t * 2 + 0]  = i0;
        idx[t * 2 + 1]  = i1;
        prob[t * 2 + 0] = p0;
        prob[t * 2 + 1] = 1.f - p0;
    }
}

// ---------------------------------------------------------------------------
// Deterministic counting sort of (token,k) slots by expert.
// ---------------------------------------------------------------------------
__global__ void zero_kernel(int* cnt) { cnt[threadIdx.x] = 0; }

__global__ void count_kernel(const int* __restrict__ idx, int* cnt) {
    int t = blockIdx.x * 256 + threadIdx.x;
    atomicAdd(&cnt[idx[2 * t]], 1);
    atomicAdd(&cnt[64 + idx[2 * t + 1]], 1);
}

// Parallel exclusive scans (128 threads: k = tid>>6, e = tid&63)
__global__ void scan_kernel(const int* __restrict__ cnt, int* off, int* poff) {
    __shared__ int s1[2][64], s2[2][64];
    int k = threadIdx.x >> 6, e = threadIdx.x & 63;
    int c  = cnt[k * 64 + e];
    int nt = (c + 7) >> 3;
    s1[k][e] = c; s2[k][e] = nt;
    __syncthreads();
    for (int d = 1; d < 64; d <<= 1) {
        int va = (e >= d) ? s1[k][e - d] : 0;
        int vb = (e >= d) ? s2[k][e - d] : 0;
        __syncthreads();
        s1[k][e] += va; s2[k][e] += vb;
        __syncthreads();
    }
    off[k * 64 + e]  = s1[k][e] - c;
    poff[k * 65 + e] = s2[k][e] - nt;
    if (e == 63) poff[k * 65 + 64] = s2[k][63];
}

// tile -> expert map via binary search in poff
__global__ void fill_tile_kernel(const int* __restrict__ poff, int* __restrict__ tileE) {
    int g = blockIdx.x * 256 + threadIdx.x;
    if (g >= 2 * 1152) return;
    int k = g / 1152, q = g - k * 1152;
    int tot = poff[k * 65 + 64];
    int e = -1;
    if (q < tot) {
        int lo = 0, hi = 64;
        while (hi - lo > 1) {
            int mid = (lo + hi) >> 1;
            if (poff[k * 65 + mid] <= q) lo = mid; else hi = mid;
        }
        e = lo;
    }
    tileE[k * 1152 + q] = e;
}

// one block per (k,expert); stable in token order -> deterministic
__global__ void scatter_kernel(const int* __restrict__ idx,
                               const int* __restrict__ off,
                               int* __restrict__ perm) {
    int k = blockIdx.x >> 6, e = blockIdx.x & 63;
    int base = off[k * 64 + e];
    __shared__ int warp_tot[8];
    __shared__ int carry;
    if (threadIdx.x == 0) carry = 0;
    __syncthreads();
    for (int t0 = 0; t0 < NTOK; t0 += 256) {
        int t = t0 + threadIdx.x;
        bool m = (idx[2 * t + k] == e);
        unsigned bal = __ballot_sync(0xffffffffu, m);
        int lane = threadIdx.x & 31, wid = threadIdx.x >> 5;
        int wpre = __popc(bal & ((1u << lane) - 1));
        if (lane == 0) warp_tot[wid] = __popc(bal);
        __syncthreads();
        int wbase = 0;
#pragma unroll
        for (int w = 0; w < 8; w++) if (w < wid) wbase += warp_tot[w];
        int tot = 0;
#pragma unroll
        for (int w = 0; w < 8; w++) tot += warp_tot[w];
        if (m) perm[k * NTOK + base + carry + wbase + wpre] = t;
        __syncthreads();
        if (threadIdx.x == 0) carry += tot;
        __syncthreads();
    }
}

// ---------------------------------------------------------------------------
// UP expert-grouped: 8 same-expert slots per CTA, 512 threads.
//   T[t] = pk * A_e @ X[t] ([64,32]@[32,32]),  Y[t] = T[t] @ B_e^T ([64,64])
// KP=0: h = Y;  KP=1: h = gelu(scale*(h + Y) + bias)
// smem floats: AsT[32][66] | BsT[32][66] | Xsn[32][264] | Ts[8][64][34]
// ---------------------------------------------------------------------------
#define UOFF_A 0
#define UOFF_B 2112
#define UOFF_X 4224
#define UOFF_T 12672
#define UP_SMEM_BYTES (30080 * 4)

template <int KP>
__global__ void __launch_bounds__(512, 1)
up_gemm(const float* __restrict__ x, const float* __restrict__ A,
        const float* __restrict__ Bw, const float* __restrict__ scale,
        const float* __restrict__ bias, const float* __restrict__ prob,
        const int* __restrict__ perm, const int* __restrict__ off,
        const int* __restrict__ poff, const int* __restrict__ cnt,
        const int* __restrict__ tileE, float* __restrict__ h)
{
    extern __shared__ float sm[];
    __shared__ int sh_e, sh_t[8], sh_v[8];
    __shared__ float sh_pk[8];
    const int tid = threadIdx.x;

    if (tid == 0) {
        int b = blockIdx.x;
        int e = tileE[KP * 1152 + b];
        sh_e = e;
        if (e >= 0) {
            int n = cnt[KP * 64 + e], base = off[KP * 64 + e];
            int l0 = (b - poff[KP * 65 + e]) * 8;
            for (int s = 0; s < 8; s++) {
                int li = l0 + s;
                if (li < n) {
                    int t = perm[KP * NTOK + base + li];
                    sh_t[s] = t; sh_v[s] = 1; sh_pk[s] = prob[2 * t + KP];
                } else { sh_t[s] = 0; sh_v[s] = 0; sh_pk[s] = 0.f; }
            }
        }
    }
    __syncthreads();
    if (sh_e < 0) return;
    const int e = sh_e;

    {   // A_e [64,32] -> AsT[i][o]; B_e [64,32] -> BsT[j][p]  (1 float4/thread)
        const float4* A4 = (const float4*)(A + e * 2048);
        const float4* B4 = (const float4*)(Bw + e * 2048);
        int o = tid >> 3, c4 = (tid & 7) * 4;
        float4 va = A4[tid], vb = B4[tid];
        sm[UOFF_A + (c4 + 0) * 66 + o] = va.x;
        sm[UOFF_A + (c4 + 1) * 66 + o] = va.y;
        sm[UOFF_A + (c4 + 2) * 66 + o] = va.z;
        sm[UOFF_A + (c4 + 3) * 66 + o] = va.w;
        sm[UOFF_B + (c4 + 0) * 66 + o] = vb.x;
        sm[UOFF_B + (c4 + 1) * 66 + o] = vb.y;
        sm[UOFF_B + (c4 + 2) * 66 + o] = vb.z;
        sm[UOFF_B + (c4 + 3) * 66 + o] = vb.w;
        // X: Xsn[i][32s + j], 4 float4/thread
#pragma unroll
        for (int r = 0; r < 4; r++) {
            int l = tid + 512 * r;
            int s = l >> 8, i = (l >> 3) & 31, j4 = (l & 7) * 4;
            *(float4*)&sm[UOFF_X + i * 264 + s * 32 + j4] =
                *(const float4*)&x[sh_t[s] * 1024 + i * 32 + j4];
        }
    }
    __syncthreads();

    {   // GEMM1: og (8 groups of 4 o-pairs), ng = j, th2 = token half
        const int og = (tid >> 5) & 7, ng = tid & 31, th2 = tid >> 8;
        u64 acc[4][4];
#pragma unroll
        for (int q = 0; q < 4; q++)
#pragma unroll
            for (int nn = 0; nn < 4; nn++) acc[q][nn] = 0ull;
#pragma unroll 8
        for (int i = 0; i < 32; i++) {
            u64 a[4];
#pragma unroll
            for (int q = 0; q < 4; q++)
                a[q] = *(const u64*)&sm[UOFF_A + i * 66 + 8 * og + 2 * q];
            u64 xv[4];
#pragma unroll
            for (int nn = 0; nn < 4; nn++)
                xv[nn] = dup2(sm[UOFF_X + i * 264 + (4 * th2 + nn) * 32 + ng]);
#pragma unroll
            for (int q = 0; q < 4; q++)
#pragma unroll
                for (int nn = 0; nn < 4; nn++)
                    ffma2(acc[q][nn], a[q], xv[nn]);
        }
#pragma unroll
        for (int q = 0; q < 4; q++)
#pragma unroll
            for (int nn = 0; nn < 4; nn++) {
                int s = 4 * th2 + nn;
                float2 f = unpk(acc[q][nn]);
                float pk = sh_pk[s];
                int o = 8 * og + 2 * q;
                sm[UOFF_T + s * 2176 + o * 34 + ng]       = f.x * pk;
                sm[UOFF_T + s * 2176 + (o + 1) * 34 + ng] = f.y * pk;
            }
    }
    __syncthreads();

    {   // GEMM2: og2 (16 groups of 4 o), ppg (8 groups of 4 p-pairs), tg: 2 tokens
        const int og2 = (tid >> 3) & 15, ppg = tid & 7, tg = tid >> 7;
        const float s0 = scale[0];
        u64 acc[4][4][2];
#pragma unroll
        for (int oo = 0; oo < 4; oo++)
#pragma unroll
            for (int qq = 0; qq < 4; qq++) { acc[oo][qq][0] = 0ull; acc[oo][qq][1] = 0ull; }
#pragma unroll 4
        for (int j = 0; j < 32; j++) {
            u64 bv[4];
#pragma unroll
            for (int qq = 0; qq < 4; qq++)
                bv[qq] = *(const u64*)&sm[UOFF_B + j * 66 + 2 * (ppg + 8 * qq)];
            u64 tv[4][2];
#pragma unroll
            for (int oo = 0; oo < 4; oo++)
#pragma unroll
                for (int tt = 0; tt < 2; tt++)
                    tv[oo][tt] = dup2(sm[UOFF_T + (2 * tg + tt) * 2176 +
                                         (og2 * 4 + oo) * 34 + j]);
#pragma unroll
            for (int oo = 0; oo < 4; oo++)
#pragma unroll
                for (int qq = 0; qq < 4; qq++)
#pragma unroll
                    for (int tt = 0; tt < 2; tt++)
                        ffma2(acc[oo][qq][tt], tv[oo][tt], bv[qq]);
        }
#pragma unroll
        for (int oo = 0; oo < 4; oo++)
#pragma unroll
            for (int qq = 0; qq < 4; qq++)
#pragma unroll
                for (int tt = 0; tt < 2; tt++) {
                    int s = 2 * tg + tt;
                    if (sh_v[s]) {
                        float2 f = unpk(acc[oo][qq][tt]);
                        int o = og2 * 4 + oo, p = 2 * (ppg + 8 * qq);
                        float* dst = h + sh_t[s] * 4096 + o * 64 + p;
                        if (KP == 0) {
                            *(float2*)dst = f;
                        } else {
                            float2 cur = *(const float2*)dst;
                            float2 bs = *(const float2*)&bias[o * 64 + p];
                            float y0 = (cur.x + f.x) * s0 + bs.x;
                            float y1 = (cur.y + f.y) * s0 + bs.y;
                            *(float2*)dst = make_float2(gelu_f(y0), gelu_f(y1));
                        }
                    }
                }
    }
}

// ---------------------------------------------------------------------------
// DOWN expert-grouped: 8 same-expert slots per CTA, 512 threads.
//   T[t] = pk * A_e @ X[t] ([32,64]@[64,64]),  Y[t] = T[t] @ B_e^T ([32,32])
// X streamed in 4 slabs of 16 rows with register prefetch.
// smem floats: AsT[64][34] | BsT[64][34] | Xs[16][520] | Ts[8][32][67]
// ---------------------------------------------------------------------------
#define DOFF_A 0
#define DOFF_B 2176
#define DOFF_X 4352
#define DOFF_T 12672
#define DN_SMEM_BYTES (29824 * 4)

template <int KP>
__global__ void __launch_bounds__(512, 1)
down_gemm(const float* __restrict__ hbuf, const float* __restrict__ A,
          const float* __restrict__ Bw, const float* __restrict__ scale,
          const float* __restrict__ bias, const float* __restrict__ prob,
          const int* __restrict__ perm, const int* __restrict__ off,
          const int* __restrict__ poff, const int* __restrict__ cnt,
          const int* __restrict__ tileE, float* __restrict__ out)
{
    extern __shared__ float sm[];
    __shared__ int sh_e, sh_t[8], sh_v[8];
    __shared__ float sh_pk[8];
    const int tid = threadIdx.x;

    if (tid == 0) {
        int b = blockIdx.x;
        int e = tileE[KP * 1152 + b];
        sh_e = e;
        if (e >= 0) {
            int n = cnt[KP * 64 + e], base = off[KP * 64 + e];
            int l0 = (b - poff[KP * 65 + e]) * 8;
            for (int s = 0; s < 8; s++) {
                int li = l0 + s;
                if (li < n) {
                    int t = perm[KP * NTOK + base + li];
                    sh_t[s] = t; sh_v[s] = 1; sh_pk[s] = prob[2 * t + KP];
                } else { sh_t[s] = 0; sh_v[s] = 0; sh_pk[s] = 0.f; }
            }
        }
    }
    __syncthreads();
    if (sh_e < 0) return;
    const int e = sh_e;

    {   // A_e [32,64] -> AsT[i][o]; B_e [32,64] -> BsT[j][p]  (1 float4/thread)
        const float4* A4 = (const float4*)(A + e * 2048);
        const float4* B4 = (const float4*)(Bw + e * 2048);
        int o = tid >> 4, c4 = (tid & 15) * 4;
        float4 va = A4[tid], vb = B4[tid];
        sm[DOFF_A + (c4 + 0) * 34 + o] = va.x;
        sm[DOFF_A + (c4 + 1) * 34 + o] = va.y;
        sm[DOFF_A + (c4 + 2) * 34 + o] = va.z;
        sm[DOFF_A + (c4 + 3) * 34 + o] = va.w;
        sm[DOFF_B + (c4 + 0) * 34 + o] = vb.x;
        sm[DOFF_B + (c4 + 1) * 34 + o] = vb.y;
        sm[DOFF_B + (c4 + 2) * 34 + o] = vb.z;
        sm[DOFF_B + (c4 + 3) * 34 + o] = vb.w;
    }

    {   // GEMM1 with X streamed in 4 slabs of 16 i-rows, register prefetch
        const int og = (tid >> 6) & 3, ng = tid & 63, th2 = tid >> 8;
        // X loader mapping: l = tid + 512r -> (i, s, j4)
        const int xs_ = (tid >> 4) & 7, xj4 = (tid & 15) * 4;
        u64 acc[4][4];
#pragma unroll
        for (int q = 0; q < 4; q++)
#pragma unroll
            for (int nn = 0; nn < 4; nn++) acc[q][nn] = 0ull;

        float4 pre[4];
#pragma unroll
        for (int r = 0; r < 4; r++) {
            int i = (tid + 512 * r) >> 7;
            pre[r] = *(const float4*)&hbuf[sh_t[xs_] * 4096 + i * 64 + xj4];
        }

#pragma unroll 1
        for (int slab = 0; slab < 4; slab++) {
            __syncthreads();
#pragma unroll
            for (int r = 0; r < 4; r++) {
                int i = ((tid + 512 * r) >> 7) & 15;
                *(float4*)&sm[DOFF_X + i * 520 + xs_ * 64 + xj4] = pre[r];
            }
            __syncthreads();
            if (slab < 3) {
#pragma unroll
                for (int r = 0; r < 4; r++) {
                    int i = ((tid + 512 * r) >> 7) & 15;
                    pre[r] = *(const float4*)&hbuf[sh_t[xs_] * 4096 +
                                                   ((slab + 1) * 16 + i) * 64 + xj4];
                }
            }
#pragma unroll 8
            for (int i = 0; i < 16; i++) {
                int gi = slab * 16 + i;
                u64 a[4];
#pragma unroll
                for (int q = 0; q < 4; q++)
                    a[q] = *(const u64*)&sm[DOFF_A + gi * 34 + 8 * og + 2 * q];
                u64 xv[4];
#pragma unroll
                for (int nn = 0; nn < 4; nn++)
                    xv[nn] = dup2(sm[DOFF_X + i * 520 + (4 * th2 + nn) * 64 + ng]);
#pragma unroll
                for (int q = 0; q < 4; q++)
#pragma unroll
                    for (int nn = 0; nn < 4; nn++)
                        ffma2(acc[q][nn], a[q], xv[nn]);
            }
        }
#pragma unroll
        for (int q = 0; q < 4; q++)
#pragma unroll
            for (int nn = 0; nn < 4; nn++) {
                int s = 4 * th2 + nn;
                float2 f = unpk(acc[q][nn]);
                float pk = sh_pk[s];
                int o = 8 * og + 2 * q;
                sm[DOFF_T + s * 2144 + o * 67 + ng]       = f.x * pk;
                sm[DOFF_T + s * 2144 + (o + 1) * 67 + ng] = f.y * pk;
            }
    }
    __syncthreads();

    {   // GEMM2: og3 (8 groups of 4 o), ppg (8 groups of 2 p-pairs), tg = token
        const int og3 = (tid >> 3) & 7, ppg = tid & 7, tg = tid >> 6;
        const float s0 = scale[0];
        u64 acc[4][2];
#pragma unroll
        for (int oo = 0; oo < 4; oo++) { acc[oo][0] = 0ull; acc[oo][1] = 0ull; }
#pragma unroll 8
        for (int j = 0; j < 64; j++) {
            u64 bv[2];
#pragma unroll
            for (int qq = 0; qq < 2; qq++)
                bv[qq] = *(const u64*)&sm[DOFF_B + j * 34 + 2 * (ppg + 8 * qq)];
            u64 tv[4];
#pragma unroll
            for (int oo = 0; oo < 4; oo++)
                tv[oo] = dup2(sm[DOFF_T + tg * 2144 + (og3 * 4 + oo) * 67 + j]);
#pragma unroll
            for (int oo = 0; oo < 4; oo++)
#pragma unroll
                for (int qq = 0; qq < 2; qq++)
                    ffma2(acc[oo][qq], tv[oo], bv[qq]);
        }
        if (sh_v[tg]) {
#pragma unroll
            for (int oo = 0; oo < 4; oo++)
#pragma unroll
                for (int qq = 0; qq < 2; qq++) {
                    float2 f = unpk(acc[oo][qq]);
                    int o = og3 * 4 + oo, p = 2 * (ppg + 8 * qq);
                    float* dst = out + sh_t[tg] * 1024 + o * 32 + p;
                    if (KP == 0) {
                        *(float2*)dst = f;
                    } else {
                        float2 cur = *(const float2*)dst;
                        float2 bs = *(const float2*)&bias[o * 32 + p];
                        *(float2*)dst = make_float2((cur.x + f.x) * s0 + bs.x,
                                                    (cur.y + f.y) * s0 + bs.y);
                    }
                }
        }
    }
}

// ---------------------------------------------------------------------------
extern "C" void kernel_launch(void* const* d_in, const int* in_sizes, int n_in,
                              void* d_out, int out_size)
{
    const float* x          = (const float*)d_in[0];
    const float* W_up       = (const float*)d_in[1];
    const float* A_up       = (const float*)d_in[2];
    const float* B_up       = (const float*)d_in[3];
    const float* scale_up   = (const float*)d_in[4];
    const float* bias_up    = (const float*)d_in[5];
    const float* W_down     = (const float*)d_in[6];
    const float* A_down     = (const float*)d_in[7];
    const float* B_down     = (const float*)d_in[8];
    const float* scale_down = (const float*)d_in[9];
    const float* bias_down  = (const float*)d_in[10];
    float* out = (float*)d_out;

    float *h, *pu, *pd;
    int *iu, *idn, *cnt, *off, *poff, *tileE, *perm;
    cudaGetSymbolAddress((void**)&h,     g_h);
    cudaGetSymbolAddress((void**)&iu,    g_idx_up);
    cudaGetSymbolAddress((void**)&pu,    g_prob_up);
    cudaGetSymbolAddress((void**)&idn,   g_idx_dn);
    cudaGetSymbolAddress((void**)&pd,    g_prob_dn);
    cudaGetSymbolAddress((void**)&cnt,   g_cnt);
    cudaGetSymbolAddress((void**)&off,   g_off);
    cudaGetSymbolAddress((void**)&poff,  g_poff);
    cudaGetSymbolAddress((void**)&tileE, g_tileE);
    cudaGetSymbolAddress((void**)&perm,  g_perm);

    cudaFuncSetAttribute(up_gemm<0>,   cudaFuncAttributeMaxDynamicSharedMemorySize, UP_SMEM_BYTES);
    cudaFuncSetAttribute(up_gemm<1>,   cudaFuncAttributeMaxDynamicSharedMemorySize, UP_SMEM_BYTES);
    cudaFuncSetAttribute(down_gemm<0>, cudaFuncAttributeMaxDynamicSharedMemorySize, DN_SMEM_BYTES);
    cudaFuncSetAttribute(down_gemm<1>, cudaFuncAttributeMaxDynamicSharedMemorySize, DN_SMEM_BYTES);

    const int GRID = 1088;  // >= max tiles per pass (1024 + 64 padding)

    // up path
    router_kernel<1024><<<NTOK / 64, 256>>>(x, W_up, iu, pu);
    zero_kernel<<<1, 128>>>(cnt);
    count_kernel<<<NTOK / 256, 256>>>(iu, cnt);
    scan_kernel<<<1, 128>>>(cnt, off, poff);
    fill_tile_kernel<<<9, 256>>>(poff, tileE);
    scatter_kernel<<<128, 256>>>(iu, off, perm);
    up_gemm<0><<<GRID, 512, UP_SMEM_BYTES>>>(x, A_up, B_up, scale_up, bias_up,
                                             pu, perm, off, poff, cnt, tileE, h);
    up_gemm<1><<<GRID, 512, UP_SMEM_BYTES>>>(x, A_up, B_up, scale_up, bias_up,
                                             pu, perm, off, poff, cnt, tileE, h);

    // down path
    router_kernel<4096><<<NTOK / 64, 256>>>(h, W_down, idn, pd);
    zero_kernel<<<1, 128>>>(cnt);
    count_kernel<<<NTOK / 256, 256>>>(idn, cnt);
    scan_kernel<<<1, 128>>>(cnt, off, poff);
    fill_tile_kernel<<<9, 256>>>(poff, tileE);
    scatter_kernel<<<128, 256>>>(idn, off, perm);
    down_gemm<0><<<GRID, 512, DN_SMEM_BYTES>>>(h, A_down, B_down, scale_down, bias_down,
                                               pd, perm, off, poff, cnt, tileE, out);
    down_gemm<1><<<GRID, 512, DN_SMEM_BYTES>>>(h, A_down, B_down, scale_down, bias_down,
                                               pd, perm, off, poff, cnt, tileE, out);
}

// round 13
// speedup vs baseline: 1.5332x; 1.0366x over previous
#include <cuda_runtime.h>
#include <math.h>

#define NTOK 8192
#define NEXP 64

typedef unsigned long long u64;

// Scratch (device globals: allocation-free)
__device__ float g_h[NTOK * 4096];
__device__ int   g_idx_up[NTOK * 2];
__device__ float g_prob_up[NTOK * 2];
__device__ int   g_idx_dn[NTOK * 2];
__device__ float g_prob_dn[NTOK * 2];
__device__ int   g_cnt[128];
__device__ int   g_off[128];
__device__ int   g_poff[132];
__device__ int   g_tileE[2 * 1152];
__device__ int   g_perm[2 * NTOK];

__device__ __forceinline__ void ffma2(u64& d, u64 a, u64 b) {
    asm("fma.rn.f32x2 %0, %1, %2, %0;" : "+l"(d) : "l"(a), "l"(b));
}
__device__ __forceinline__ float hadd(u64 a) {
    float lo, hi;
    asm("mov.b64 {%0,%1}, %2;" : "=f"(lo), "=f"(hi) : "l"(a));
    return lo + hi;
}
__device__ __forceinline__ float gelu_f(float y) {
    return 0.5f * y * (1.f + erff(y * 0.70710678118654752f));
}

// ---- tf32x3: operand split + compensated mma ------------------------------
struct tf2 { unsigned h, l; };
__device__ __forceinline__ tf2 spl(float x) {
    tf2 r;
    asm("cvt.rna.tf32.f32 %0, %1;" : "=r"(r.h) : "f"(x));
    float hf = __uint_as_float(r.h);
    asm("cvt.rna.tf32.f32 %0, %1;" : "=r"(r.l) : "f"(x - hf));
    return r;
}
__device__ __forceinline__ void mma8(float* d, const unsigned* a, const unsigned* b) {
    asm("mma.sync.aligned.m16n8k8.row.col.f32.tf32.tf32.f32 "
        "{%0,%1,%2,%3}, {%4,%5,%6,%7}, {%8,%9}, {%0,%1,%2,%3};"
        : "+f"(d[0]), "+f"(d[1]), "+f"(d[2]), "+f"(d[3])
        : "r"(a[0]), "r"(a[1]), "r"(a[2]), "r"(a[3]), "r"(b[0]), "r"(b[1]));
}
__device__ __forceinline__ void mma3(float* d, const tf2* a, const tf2* b) {
    unsigned ah[4] = {a[0].h, a[1].h, a[2].h, a[3].h};
    unsigned al[4] = {a[0].l, a[1].l, a[2].l, a[3].l};
    unsigned bh[2] = {b[0].h, b[1].h};
    unsigned bl[2] = {b[0].l, b[1].l};
    mma8(d, ah, bh);
    mma8(d, al, bh);
    mma8(d, ah, bl);
}

// ---------------------------------------------------------------------------
// Router (fp32, unchanged): logits = x @ W^T, fused top-2 + softmax.
// ---------------------------------------------------------------------------
template <int D>
__global__ void __launch_bounds__(256, 2)
router_kernel(const float* __restrict__ x, const float* __restrict__ W,
              int* __restrict__ idx, float* __restrict__ prob)
{
    __shared__ float xs[64][36];
    __shared__ float ws[64][36];
    __shared__ float ls[64][65];

    const int tid  = threadIdx.x;
    const int tok0 = blockIdx.x * 64;
    const int tr   = (tid >> 4) * 4;
    const int eb   = tid & 15;

    u64 acc[4][4];
#pragma unroll
    for (int i = 0; i < 4; i++)
#pragma unroll
        for (int j = 0; j < 4; j++) acc[i][j] = 0ull;

    for (int d0 = 0; d0 < D; d0 += 32) {
        {
            int l = tid;
            int r = l >> 3, c4 = (l & 7) * 4;
            *(float4*)&xs[r][c4] = *(const float4*)&x[(tok0 + r) * D + d0 + c4];
            *(float4*)&ws[r][c4] = *(const float4*)&W[r * D + d0 + c4];
            l += 256;
            r = l >> 3; c4 = (l & 7) * 4;
            *(float4*)&xs[r][c4] = *(const float4*)&x[(tok0 + r) * D + d0 + c4];
            *(float4*)&ws[r][c4] = *(const float4*)&W[r * D + d0 + c4];
        }
        __syncthreads();
#pragma unroll
        for (int d4 = 0; d4 < 32; d4 += 4) {
            ulonglong2 xa[4], wb[4];
#pragma unroll
            for (int i = 0; i < 4; i++)
                xa[i] = *(const ulonglong2*)&xs[tr + i][d4];
#pragma unroll
            for (int j = 0; j < 4; j++)
                wb[j] = *(const ulonglong2*)&ws[eb + 16 * j][d4];
#pragma unroll
            for (int i = 0; i < 4; i++)
#pragma unroll
                for (int j = 0; j < 4; j++) {
                    ffma2(acc[i][j], xa[i].x, wb[j].x);
                    ffma2(acc[i][j], xa[i].y, wb[j].y);
                }
        }
        __syncthreads();
    }

#pragma unroll
    for (int i = 0; i < 4; i++)
#pragma unroll
        for (int j = 0; j < 4; j++)
            ls[tr + i][eb + 16 * j] = hadd(acc[i][j]);
    __syncthreads();

    if (tid < 64) {
        float v0 = -INFINITY, v1 = -INFINITY;
        int i0 = 0, i1 = 0;
        for (int e = 0; e < NEXP; e++) {
            float v = ls[tid][e];
            if (v > v0) { v1 = v0; i1 = i0; v0 = v; i0 = e; }
            else if (v > v1) { v1 = v; i1 = e; }
        }
        float e1 = expf(v1 - v0);
        float p0 = 1.f / (1.f + e1);
        int t = tok0 + tid;
        idx[t * 2 + 0]  = i0;
        idx[t * 2 + 1]  = i1;
        prob[t * 2 + 0] = p0;
        prob[t * 2 + 1] = 1.f - p0;
    }
}

// ---------------------------------------------------------------------------
// Deterministic counting sort of (token,k) slots by expert.
// ---------------------------------------------------------------------------
__global__ void zero_kernel(int* cnt) { cnt[threadIdx.x] = 0; }

__global__ void count_kernel(const int* __restrict__ idx, int* cnt) {
    int t = blockIdx.x * 256 + threadIdx.x;
    atomicAdd(&cnt[idx[2 * t]], 1);
    atomicAdd(&cnt[64 + idx[2 * t + 1]], 1);
}

__global__ void scan_kernel(const int* __restrict__ cnt, int* off, int* poff) {
    __shared__ int s1[2][64], s2[2][64];
    int k = threadIdx.x >> 6, e = threadIdx.x & 63;
    int c  = cnt[k * 64 + e];
    int nt = (c + 7) >> 3;
    s1[k][e] = c; s2[k][e] = nt;
    __syncthreads();
    for (int d = 1; d < 64; d <<= 1) {
        int va = (e >= d) ? s1[k][e - d] : 0;
        int vb = (e >= d) ? s2[k][e - d] : 0;
        __syncthreads();
        s1[k][e] += va; s2[k][e] += vb;
        __syncthreads();
    }
    off[k * 64 + e]  = s1[k][e] - c;
    poff[k * 65 + e] = s2[k][e] - nt;
    if (e == 63) poff[k * 65 + 64] = s2[k][63];
}

__global__ void fill_tile_kernel(const int* __restrict__ poff, int* __restrict__ tileE) {
    int g = blockIdx.x * 256 + threadIdx.x;
    if (g >= 2 * 1152) return;
    int k = g / 1152, q = g - k * 1152;
    int tot = poff[k * 65 + 64];
    int e = -1;
    if (q < tot) {
        int lo = 0, hi = 64;
        while (hi - lo > 1) {
            int mid = (lo + hi) >> 1;
            if (poff[k * 65 + mid] <= q) lo = mid; else hi = mid;
        }
        e = lo;
    }
    tileE[k * 1152 + q] = e;
}

__global__ void scatter_kernel(const int* __restrict__ idx,
                               const int* __restrict__ off,
                               int* __restrict__ perm) {
    int k = blockIdx.x >> 6, e = blockIdx.x & 63;
    int base = off[k * 64 + e];
    __shared__ int warp_tot[8];
    __shared__ int carry;
    if (threadIdx.x == 0) carry = 0;
    __syncthreads();
    for (int t0 = 0; t0 < NTOK; t0 += 256) {
        int t = t0 + threadIdx.x;
        bool m = (idx[2 * t + k] == e);
        unsigned bal = __ballot_sync(0xffffffffu, m);
        int lane = threadIdx.x & 31, wid = threadIdx.x >> 5;
        int wpre = __popc(bal & ((1u << lane) - 1));
        if (lane == 0) warp_tot[wid] = __popc(bal);
        __syncthreads();
        int wbase = 0;
#pragma unroll
        for (int w = 0; w < 8; w++) if (w < wid) wbase += warp_tot[w];
        int tot = 0;
#pragma unroll
        for (int w = 0; w < 8; w++) tot += warp_tot[w];
        if (m) perm[k * NTOK + base + carry + wbase + wpre] = t;
        __syncthreads();
        if (threadIdx.x == 0) carry += tot;
        __syncthreads();
    }
}

// ---------------------------------------------------------------------------
// UP (tf32x3 tensor): 8 same-expert slots per CTA, 512 threads = 16 warps.
//  GEMM1: C[64, 256] = A[64,32] @ Xc[32, 256]   (n = s*32 + j), T = pk*C
//  GEMM2: Y[512, 64] = Tflat[512,32] @ B^T      (m = s*64 + o)
// smem floats (raw fp32): As[64][36] | BsT[32][72] | Xs[32][264] | Tf[512][36]
// ---------------------------------------------------------------------------
#define UA 0
#define UB 2304
#define UX 4608
#define UT 13056
#define UP_SMEM_BYTES (31488 * 4)

template <int KP>
__global__ void __launch_bounds__(512, 1)
up_gemm(const float* __restrict__ x, const float* __restrict__ A,
        const float* __restrict__ Bw, const float* __restrict__ scale,
        const float* __restrict__ bias, const float* __restrict__ prob,
        const int* __restrict__ perm, const int* __restrict__ off,
        const int* __restrict__ poff, const int* __restrict__ cnt,
        const int* __restrict__ tileE, float* __restrict__ h)
{
    extern __shared__ float sm[];
    __shared__ int sh_e, sh_t[8], sh_v[8];
    __shared__ float sh_pk[8];
    const int tid = threadIdx.x;
    const int lane = tid & 31, w = tid >> 5;
    const int g = lane >> 2, tq = lane & 3;

    if (tid == 0) {
        int b = blockIdx.x;
        int e = tileE[KP * 1152 + b];
        sh_e = e;
        if (e >= 0) {
            int n = cnt[KP * 64 + e], base = off[KP * 64 + e];
            int l0 = (b - poff[KP * 65 + e]) * 8;
            for (int s = 0; s < 8; s++) {
                int li = l0 + s;
                if (li < n) {
                    int t = perm[KP * NTOK + base + li];
                    sh_t[s] = t; sh_v[s] = 1; sh_pk[s] = prob[2 * t + KP];
                } else { sh_t[s] = 0; sh_v[s] = 0; sh_pk[s] = 0.f; }
            }
        }
    }
    __syncthreads();
    if (sh_e < 0) return;
    const int e = sh_e;

    {   // stage raw fp32: A[o][i] s36, B^T[j][p] s72, X[i][s*32+j] s264
        const float4* A4 = (const float4*)(A + e * 2048);
        const float4* B4 = (const float4*)(Bw + e * 2048);
        int o = tid >> 3, c4 = (tid & 7) * 4;
        float4 va = A4[tid], vb = B4[tid];
        *(float4*)&sm[UA + o * 36 + c4] = va;
        sm[UB + (c4 + 0) * 72 + o] = vb.x;
        sm[UB + (c4 + 1) * 72 + o] = vb.y;
        sm[UB + (c4 + 2) * 72 + o] = vb.z;
        sm[UB + (c4 + 3) * 72 + o] = vb.w;
#pragma unroll
        for (int r = 0; r < 4; r++) {
            int l = tid + 512 * r;
            int s = l >> 8, i = (l >> 3) & 31, j4 = (l & 7) * 4;
            *(float4*)&sm[UX + i * 264 + s * 32 + j4] =
                *(const float4*)&x[sh_t[s] * 1024 + i * 32 + j4];
        }
    }
    __syncthreads();

    {   // GEMM1: mw = w&3 (m-tile), nw = w>>2 (64-col n-super)
        const int mw = w & 3, nw = w >> 2;
        float acc[8][4];
#pragma unroll
        for (int nt = 0; nt < 8; nt++)
#pragma unroll
            for (int q = 0; q < 4; q++) acc[nt][q] = 0.f;
#pragma unroll
        for (int ks = 0; ks < 4; ks++) {
            tf2 a[4];
            int ro = mw * 16 + g, ci = ks * 8 + tq;
            a[0] = spl(sm[UA + ro * 36 + ci]);
            a[1] = spl(sm[UA + (ro + 8) * 36 + ci]);
            a[2] = spl(sm[UA + ro * 36 + ci + 4]);
            a[3] = spl(sm[UA + (ro + 8) * 36 + ci + 4]);
#pragma unroll
            for (int nt = 0; nt < 8; nt++) {
                tf2 b[2];
                int n = nw * 64 + nt * 8 + g;
                b[0] = spl(sm[UX + (ks * 8 + tq) * 264 + n]);
                b[1] = spl(sm[UX + (ks * 8 + tq + 4) * 264 + n]);
                mma3(acc[nt], a, b);
            }
        }
        // epilogue: T = pk * C (raw fp32) -> Tflat[(s*64+m)][j] stride 36
#pragma unroll
        for (int nt = 0; nt < 8; nt++) {
            int n0 = nw * 64 + nt * 8 + 2 * tq;
            int s = n0 >> 5, j = n0 & 31;
            float pk = sh_pk[s];
            int m0 = mw * 16 + g;
            *(float2*)&sm[UT + (s * 64 + m0) * 36 + j] =
                make_float2(acc[nt][0] * pk, acc[nt][1] * pk);
            *(float2*)&sm[UT + (s * 64 + m0 + 8) * 36 + j] =
                make_float2(acc[nt][2] * pk, acc[nt][3] * pk);
        }
    }
    __syncthreads();

    {   // GEMM2: warp w -> m-tiles {2w, 2w+1} (token s = w>>1), 8 n-tiles in 2 chunks
        const int s = w >> 1;
        const float s0 = scale[0];
        float* hrow = h + sh_t[s] * 4096;
#pragma unroll 1
        for (int nc = 0; nc < 2; nc++) {
            float acc[2][4][4];
#pragma unroll
            for (int mm = 0; mm < 2; mm++)
#pragma unroll
                for (int nt = 0; nt < 4; nt++)
#pragma unroll
                    for (int q = 0; q < 4; q++) acc[mm][nt][q] = 0.f;
#pragma unroll
            for (int ks = 0; ks < 4; ks++) {
                tf2 a[2][4];
#pragma unroll
                for (int mm = 0; mm < 2; mm++) {
                    int m0 = (2 * w + mm) * 16 + g, cj = ks * 8 + tq;
                    a[mm][0] = spl(sm[UT + m0 * 36 + cj]);
                    a[mm][1] = spl(sm[UT + (m0 + 8) * 36 + cj]);
                    a[mm][2] = spl(sm[UT + m0 * 36 + cj + 4]);
                    a[mm][3] = spl(sm[UT + (m0 + 8) * 36 + cj + 4]);
                }
#pragma unroll
                for (int nt = 0; nt < 4; nt++) {
                    tf2 b[2];
                    int p = (nc * 4 + nt) * 8 + g;
                    b[0] = spl(sm[UB + (ks * 8 + tq) * 72 + p]);
                    b[1] = spl(sm[UB + (ks * 8 + tq + 4) * 72 + p]);
                    mma3(acc[0][nt], a[0], b);
                    mma3(acc[1][nt], a[1], b);
                }
            }
            if (sh_v[s]) {
#pragma unroll
                for (int mm = 0; mm < 2; mm++) {
                    int m0 = (2 * w + mm) * 16 + g;
#pragma unroll
                    for (int hh = 0; hh < 2; hh++) {
                        int o = (m0 + 8 * hh) & 63;
#pragma unroll
                        for (int nt = 0; nt < 4; nt++) {
                            int p = (nc * 4 + nt) * 8 + 2 * tq;
                            float c0 = acc[mm][nt][2 * hh], c1 = acc[mm][nt][2 * hh + 1];
                            float* dst = hrow + o * 64 + p;
                            if (KP == 0) {
                                *(float2*)dst = make_float2(c0, c1);
                            } else {
                                float2 cur = *(const float2*)dst;
                                float2 bs = *(const float2*)&bias[o * 64 + p];
                                float y0 = (cur.x + c0) * s0 + bs.x;
                                float y1 = (cur.y + c1) * s0 + bs.y;
                                *(float2*)dst = make_float2(gelu_f(y0), gelu_f(y1));
                            }
                        }
                    }
                }
            }
        }
    }
}

// ---------------------------------------------------------------------------
// DOWN (tf32x3 tensor): 8 same-expert slots per CTA, 512 threads.
//  GEMM1: C[32, 512] = A[32,64] @ Xc[64, 512]  (n = s*64 + j), T = pk*C
//  GEMM2: Y[256, 32] = Tflat[256,64] @ B^T     (m = s*32 + o)
// X streamed in 4 slabs of 16 rows with register prefetch.
// smem floats (raw fp32): As[32][68] | BsT[64][40] | Xs[16][520] | Tf[256][68]
// ---------------------------------------------------------------------------
#define DA 0
#define DB 2176
#define DX 4736
#define DT 13056
#define DN_SMEM_BYTES (30464 * 4)

template <int KP>
__global__ void __launch_bounds__(512, 1)
down_gemm(const float* __restrict__ hbuf, const float* __restrict__ A,
          const float* __restrict__ Bw, const float* __restrict__ scale,
          const float* __restrict__ bias, const float* __restrict__ prob,
          const int* __restrict__ perm, const int* __restrict__ off,
          const int* __restrict__ poff, const int* __restrict__ cnt,
          const int* __restrict__ tileE, float* __restrict__ out)
{
    extern __shared__ float sm[];
    __shared__ int sh_e, sh_t[8], sh_v[8];
    __shared__ float sh_pk[8];
    const int tid = threadIdx.x;
    const int lane = tid & 31, w = tid >> 5;
    const int g = lane >> 2, tq = lane & 3;

    if (tid == 0) {
        int b = blockIdx.x;
        int e = tileE[KP * 1152 + b];
        sh_e = e;
        if (e >= 0) {
            int n = cnt[KP * 64 + e], base = off[KP * 64 + e];
            int l0 = (b - poff[KP * 65 + e]) * 8;
            for (int s = 0; s < 8; s++) {
                int li = l0 + s;
                if (li < n) {
                    int t = perm[KP * NTOK + base + li];
                    sh_t[s] = t; sh_v[s] = 1; sh_pk[s] = prob[2 * t + KP];
                } else { sh_t[s] = 0; sh_v[s] = 0; sh_pk[s] = 0.f; }
            }
        }
    }
    __syncthreads();
    if (sh_e < 0) return;
    const int e = sh_e;

    {   // stage raw fp32: A[o][i] s68, B^T[j][p] s40
        const float4* A4 = (const float4*)(A + e * 2048);
        const float4* B4 = (const float4*)(Bw + e * 2048);
        int o = tid >> 4, c4 = (tid & 15) * 4;
        float4 va = A4[tid], vb = B4[tid];
        *(float4*)&sm[DA + o * 68 + c4] = va;
        sm[DB + (c4 + 0) * 40 + o] = vb.x;
        sm[DB + (c4 + 1) * 40 + o] = vb.y;
        sm[DB + (c4 + 2) * 40 + o] = vb.z;
        sm[DB + (c4 + 3) * 40 + o] = vb.w;
    }

    {   // GEMM1: warp w owns n-super [32w, 32w+32), both m-tiles; X slab-streamed
        const int xs_ = (tid >> 4) & 7, xj4 = (tid & 15) * 4;
        float acc[2][4][4];
#pragma unroll
        for (int mm = 0; mm < 2; mm++)
#pragma unroll
            for (int nt = 0; nt < 4; nt++)
#pragma unroll
                for (int q = 0; q < 4; q++) acc[mm][nt][q] = 0.f;

        float4 pre[4];
#pragma unroll
        for (int r = 0; r < 4; r++) {
            int i = ((tid + 512 * r) >> 7) & 15;
            pre[r] = *(const float4*)&hbuf[sh_t[xs_] * 4096 + i * 64 + xj4];
        }

#pragma unroll 1
        for (int slab = 0; slab < 4; slab++) {
            __syncthreads();
#pragma unroll
            for (int r = 0; r < 4; r++) {
                int i = ((tid + 512 * r) >> 7) & 15;
                *(float4*)&sm[DX + i * 520 + xs_ * 64 + xj4] = pre[r];
            }
            __syncthreads();
            if (slab < 3) {
#pragma unroll
                for (int r = 0; r < 4; r++) {
                    int i = ((tid + 512 * r) >> 7) & 15;
                    pre[r] = *(const float4*)&hbuf[sh_t[xs_] * 4096 +
                                                   ((slab + 1) * 16 + i) * 64 + xj4];
                }
            }
#pragma unroll
            for (int kl = 0; kl < 2; kl++) {
                int gi = slab * 16 + kl * 8;
                tf2 a[2][4];
#pragma unroll
                for (int mm = 0; mm < 2; mm++) {
                    int ro = mm * 16 + g;
                    a[mm][0] = spl(sm[DA + ro * 68 + gi + tq]);
                    a[mm][1] = spl(sm[DA + (ro + 8) * 68 + gi + tq]);
                    a[mm][2] = spl(sm[DA + ro * 68 + gi + tq + 4]);
                    a[mm][3] = spl(sm[DA + (ro + 8) * 68 + gi + tq + 4]);
                }
#pragma unroll
                for (int nt = 0; nt < 4; nt++) {
                    tf2 b[2];
                    int n = w * 32 + nt * 8 + g;
                    b[0] = spl(sm[DX + (kl * 8 + tq) * 520 + n]);
                    b[1] = spl(sm[DX + (kl * 8 + tq + 4) * 520 + n]);
                    mma3(acc[0][nt], a[0], b);
                    mma3(acc[1][nt], a[1], b);
                }
            }
        }
        // epilogue: T = pk * C (raw) -> Tflat[(s*32+o)][j] stride 68
        const int s = w >> 1;
        const float pk = sh_pk[s];
#pragma unroll
        for (int mm = 0; mm < 2; mm++) {
            int o0 = mm * 16 + g;
#pragma unroll
            for (int nt = 0; nt < 4; nt++) {
                int n0 = w * 32 + nt * 8 + 2 * tq;
                int j = n0 & 63;
                *(float2*)&sm[DT + (s * 32 + o0) * 68 + j] =
                    make_float2(acc[mm][nt][0] * pk, acc[mm][nt][1] * pk);
                *(float2*)&sm[DT + (s * 32 + o0 + 8) * 68 + j] =
                    make_float2(acc[mm][nt][2] * pk, acc[mm][nt][3] * pk);
            }
        }
    }
    __syncthreads();

    {   // GEMM2: warp w owns m-tile w (token s = w>>1), 4 n-tiles, K=64
        float acc[4][4];
#pragma unroll
        for (int nt = 0; nt < 4; nt++)
#pragma unroll
            for (int q = 0; q < 4; q++) acc[nt][q] = 0.f;
#pragma unroll
        for (int ks = 0; ks < 8; ks++) {
            tf2 a[4];
            int m0 = w * 16 + g, cj = ks * 8 + tq;
            a[0] = spl(sm[DT + m0 * 68 + cj]);
            a[1] = spl(sm[DT + (m0 + 8) * 68 + cj]);
            a[2] = spl(sm[DT + m0 * 68 + cj + 4]);
            a[3] = spl(sm[DT + (m0 + 8) * 68 + cj + 4]);
#pragma unroll
            for (int nt = 0; nt < 4; nt++) {
                tf2 b[2];
                int p = nt * 8 + g;
                b[0] = spl(sm[DB + (ks * 8 + tq) * 40 + p]);
                b[1] = spl(sm[DB + (ks * 8 + tq + 4) * 40 + p]);
                mma3(acc[nt], a, b);
            }
        }
        const int s = w >> 1;
        if (sh_v[s]) {
            const float s0 = scale[0];
            float* orow = out + sh_t[s] * 1024;
            int m0 = w * 16 + g;
#pragma unroll
            for (int hh = 0; hh < 2; hh++) {
                int o = (m0 + 8 * hh) & 31;
#pragma unroll
                for (int nt = 0; nt < 4; nt++) {
                    int p = nt * 8 + 2 * tq;
                    float c0 = acc[nt][2 * hh], c1 = acc[nt][2 * hh + 1];
                    float* dst = orow + o * 32 + p;
                    if (KP == 0) {
                        *(float2*)dst = make_float2(c0, c1);
                    } else {
                        float2 cur = *(const float2*)dst;
                        float2 bs = *(const float2*)&bias[o * 32 + p];
                        *(float2*)dst = make_float2((cur.x + c0) * s0 + bs.x,
                                                    (cur.y + c1) * s0 + bs.y);
                    }
                }
            }
        }
    }
}

// ---------------------------------------------------------------------------
extern "C" void kernel_launch(void* const* d_in, const int* in_sizes, int n_in,
                              void* d_out, int out_size)
{
    const float* x          = (const float*)d_in[0];
    const float* W_up       = (const float*)d_in[1];
    const float* A_up       = (const float*)d_in[2];
    const float* B_up       = (const float*)d_in[3];
    const float* scale_up   = (const float*)d_in[4];
    const float* bias_up    = (const float*)d_in[5];
    const float* W_down     = (const float*)d_in[6];
    const float* A_down     = (const float*)d_in[7];
    const float* B_down     = (const float*)d_in[8];
    const float* scale_down = (const float*)d_in[9];
    const float* bias_down  = (const float*)d_in[10];
    float* out = (float*)d_out;

    float *h, *pu, *pd;
    int *iu, *idn, *cnt, *off, *poff, *tileE, *perm;
    cudaGetSymbolAddress((void**)&h,     g_h);
    cudaGetSymbolAddress((void**)&iu,    g_idx_up);
    cudaGetSymbolAddress((void**)&pu,    g_prob_up);
    cudaGetSymbolAddress((void**)&idn,   g_idx_dn);
    cudaGetSymbolAddress((void**)&pd,    g_prob_dn);
    cudaGetSymbolAddress((void**)&cnt,   g_cnt);
    cudaGetSymbolAddress((void**)&off,   g_off);
    cudaGetSymbolAddress((void**)&poff,  g_poff);
    cudaGetSymbolAddress((void**)&tileE, g_tileE);
    cudaGetSymbolAddress((void**)&perm,  g_perm);

    cudaFuncSetAttribute(up_gemm<0>,   cudaFuncAttributeMaxDynamicSharedMemorySize, UP_SMEM_BYTES);
    cudaFuncSetAttribute(up_gemm<1>,   cudaFuncAttributeMaxDynamicSharedMemorySize, UP_SMEM_BYTES);
    cudaFuncSetAttribute(down_gemm<0>, cudaFuncAttributeMaxDynamicSharedMemorySize, DN_SMEM_BYTES);
    cudaFuncSetAttribute(down_gemm<1>, cudaFuncAttributeMaxDynamicSharedMemorySize, DN_SMEM_BYTES);

    const int GRID = 1088;

    // up path
    router_kernel<1024><<<NTOK / 64, 256>>>(x, W_up, iu, pu);
    zero_kernel<<<1, 128>>>(cnt);
    count_kernel<<<NTOK / 256, 256>>>(iu, cnt);
    scan_kernel<<<1, 128>>>(cnt, off, poff);
    fill_tile_kernel<<<9, 256>>>(poff, tileE);
    scatter_kernel<<<128, 256>>>(iu, off, perm);
    up_gemm<0><<<GRID, 512, UP_SMEM_BYTES>>>(x, A_up, B_up, scale_up, bias_up,
                                             pu, perm, off, poff, cnt, tileE, h);
    up_gemm<1><<<GRID, 512, UP_SMEM_BYTES>>>(x, A_up, B_up, scale_up, bias_up,
                                             pu, perm, off, poff, cnt, tileE, h);

    // down path
    router_kernel<4096><<<NTOK / 64, 256>>>(h, W_down, idn, pd);
    zero_kernel<<<1, 128>>>(cnt);
    count_kernel<<<NTOK / 256, 256>>>(idn, cnt);
    scan_kernel<<<1, 128>>>(cnt, off, poff);
    fill_tile_kernel<<<9, 256>>>(poff, tileE);
    scatter_kernel<<<128, 256>>>(idn, off, perm);
    down_gemm<0><<<GRID, 512, DN_SMEM_BYTES>>>(h, A_down, B_down, scale_down, bias_down,
                                               pd, perm, off, poff, cnt, tileE, out);
    down_gemm<1><<<GRID, 512, DN_SMEM_BYTES>>>(h, A_down, B_down, scale_down, bias_down,
                                               pd, perm, off, poff, cnt, tileE, out);
}

// round 15
// speedup vs baseline: 1.5963x; 1.0412x over previous
#include <cuda_runtime.h>
#include <math.h>

#define NTOK 8192
#define NEXP 64

typedef unsigned long long u64;

// Scratch (device globals: allocation-free)
__device__ float g_h[NTOK * 4096];
__device__ int   g_idx_up[NTOK * 2];
__device__ float g_prob_up[NTOK * 2];
__device__ int   g_idx_dn[NTOK * 2];
__device__ float g_prob_dn[NTOK * 2];
__device__ int   g_cnt[128];
__device__ int   g_off[128];
__device__ int   g_poff[132];
__device__ int   g_tileE[2 * 1152];
__device__ int   g_perm[2 * NTOK];
__device__ float g_WhU[64 * 1024];
__device__ float g_WlU[64 * 1024];
__device__ float g_WhD[64 * 4096];
__device__ float g_WlD[64 * 4096];

__device__ __forceinline__ float gelu_f(float y) {
    return 0.5f * y * (1.f + erff(y * 0.70710678118654752f));
}

// ---- tf32x3: operand split + compensated mma ------------------------------
struct tf2 { unsigned h, l; };
__device__ __forceinline__ tf2 spl(float x) {
    tf2 r;
    asm("cvt.rna.tf32.f32 %0, %1;" : "=r"(r.h) : "f"(x));
    float hf = __uint_as_float(r.h);
    asm("cvt.rna.tf32.f32 %0, %1;" : "=r"(r.l) : "f"(x - hf));
    return r;
}
__device__ __forceinline__ void mma8(float* d, const unsigned* a, const unsigned* b) {
    asm("mma.sync.aligned.m16n8k8.row.col.f32.tf32.tf32.f32 "
        "{%0,%1,%2,%3}, {%4,%5,%6,%7}, {%8,%9}, {%0,%1,%2,%3};"
        : "+f"(d[0]), "+f"(d[1]), "+f"(d[2]), "+f"(d[3])
        : "r"(a[0]), "r"(a[1]), "r"(a[2]), "r"(a[3]), "r"(b[0]), "r"(b[1]));
}
__device__ __forceinline__ void mma3(float* d, const tf2* a, const tf2* b) {
    unsigned ah[4] = {a[0].h, a[1].h, a[2].h, a[3].h};
    unsigned al[4] = {a[0].l, a[1].l, a[2].l, a[3].l};
    unsigned bh[2] = {b[0].h, b[1].h};
    unsigned bl[2] = {b[0].l, b[1].l};
    mma8(d, ah, bh);
    mma8(d, al, bh);
    mma8(d, ah, bl);
}

// ---------------------------------------------------------------------------
// W pre-split: Wh = tf32(W), Wl = tf32(W - Wh)
// ---------------------------------------------------------------------------
__global__ void split_w(const float* __restrict__ W, float* __restrict__ Wh,
                        float* __restrict__ Wl, int n)
{
    int i = blockIdx.x * 256 + threadIdx.x;
    if (i < n) {
        tf2 r = spl(W[i]);
        Wh[i] = __uint_as_float(r.h);
        Wl[i] = __uint_as_float(r.l);
    }
}

// ---------------------------------------------------------------------------
// Router (tf32x3 mma): logits = x @ W^T, fused top-2 + softmax + expert count.
// 64 tokens x 64 experts per CTA, 256 threads = 8 warps.
// dyn smem floats: xh[64][36] | xl[64][36] | wh[64][36] | wl[64][36] | ls[64][66]
// ---------------------------------------------------------------------------
#define RXH 0
#define RXL 2304
#define RWH 4608
#define RWL 6912
#define RLS 9216
#define R_SMEM_BYTES (13440 * 4)

template <int D>
__global__ void __launch_bounds__(256, 2)
router_kernel(const float* __restrict__ x,
              const float* __restrict__ Wh, const float* __restrict__ Wl,
              int* __restrict__ idx, float* __restrict__ prob, int* __restrict__ cnt)
{
    extern __shared__ float sm[];
    const int tid  = threadIdx.x;
    const int tok0 = blockIdx.x * 64;
    const int lane = tid & 31, w = tid >> 5;
    const int g = lane >> 2, tq = lane & 3;
    const int mw = w & 3, nh = w >> 2;

    float acc[4][4];
#pragma unroll
    for (int nt = 0; nt < 4; nt++)
#pragma unroll
        for (int q = 0; q < 4; q++) acc[nt][q] = 0.f;

    for (int d0 = 0; d0 < D; d0 += 32) {
        __syncthreads();
#pragma unroll
        for (int li = 0; li < 2; li++) {
            int l = tid + 256 * li;
            int r = l >> 3, c4 = (l & 7) * 4;
            float4 xv = *(const float4*)&x[(tok0 + r) * D + d0 + c4];
            tf2 s0 = spl(xv.x), s1 = spl(xv.y), s2 = spl(xv.z), s3 = spl(xv.w);
            float* xhp = &sm[RXH + r * 36 + c4];
            float* xlp = &sm[RXL + r * 36 + c4];
            xhp[0] = __uint_as_float(s0.h); xlp[0] = __uint_as_float(s0.l);
            xhp[1] = __uint_as_float(s1.h); xlp[1] = __uint_as_float(s1.l);
            xhp[2] = __uint_as_float(s2.h); xlp[2] = __uint_as_float(s2.l);
            xhp[3] = __uint_as_float(s3.h); xlp[3] = __uint_as_float(s3.l);
            *(float4*)&sm[RWH + r * 36 + c4] = *(const float4*)&Wh[r * D + d0 + c4];
            *(float4*)&sm[RWL + r * 36 + c4] = *(const float4*)&Wl[r * D + d0 + c4];
        }
        __syncthreads();

#pragma unroll
        for (int ks = 0; ks < 4; ks++) {
            int ci = ks * 8 + tq;
            int ro = mw * 16 + g;
            unsigned ah[4], al[4];
            ah[0] = __float_as_uint(sm[RXH + ro * 36 + ci]);
            ah[1] = __float_as_uint(sm[RXH + (ro + 8) * 36 + ci]);
            ah[2] = __float_as_uint(sm[RXH + ro * 36 + ci + 4]);
            ah[3] = __float_as_uint(sm[RXH + (ro + 8) * 36 + ci + 4]);
            al[0] = __float_as_uint(sm[RXL + ro * 36 + ci]);
            al[1] = __float_as_uint(sm[RXL + (ro + 8) * 36 + ci]);
            al[2] = __float_as_uint(sm[RXL + ro * 36 + ci + 4]);
            al[3] = __float_as_uint(sm[RXL + (ro + 8) * 36 + ci + 4]);
#pragma unroll
            for (int nt = 0; nt < 4; nt++) {
                int n = nh * 32 + nt * 8 + g;
                unsigned bh[2], bl[2];
                bh[0] = __float_as_uint(sm[RWH + n * 36 + ci]);
                bh[1] = __float_as_uint(sm[RWH + n * 36 + ci + 4]);
                bl[0] = __float_as_uint(sm[RWL + n * 36 + ci]);
                bl[1] = __float_as_uint(sm[RWL + n * 36 + ci + 4]);
                mma8(acc[nt], ah, bh);
                mma8(acc[nt], al, bh);
                mma8(acc[nt], ah, bl);
            }
        }
    }

    // write logits to ls[64][66]
    {
        int row = mw * 16 + g;
#pragma unroll
        for (int nt = 0; nt < 4; nt++) {
            int n0 = nh * 32 + nt * 8 + 2 * tq;
            *(float2*)&sm[RLS + row * 66 + n0]       = make_float2(acc[nt][0], acc[nt][1]);
            *(float2*)&sm[RLS + (row + 8) * 66 + n0] = make_float2(acc[nt][2], acc[nt][3]);
        }
    }
    __syncthreads();

    if (tid < 64) {
        float v0 = -INFINITY, v1 = -INFINITY;
        int i0 = 0, i1 = 0;
        const float* lrow = &sm[RLS + tid * 66];
        for (int e = 0; e < NEXP; e++) {
            float v = lrow[e];
            if (v > v0) { v1 = v0; i1 = i0; v0 = v; i0 = e; }
            else if (v > v1) { v1 = v; i1 = e; }
        }
        float e1 = expf(v1 - v0);
        float p0 = 1.f / (1.f + e1);
        int t = tok0 + tid;
        idx[t * 2 + 0]  = i0;
        idx[t * 2 + 1]  = i1;
        prob[t * 2 + 0] = p0;
        prob[t * 2 + 1] = 1.f - p0;
        atomicAdd(&cnt[i0], 1);
        atomicAdd(&cnt[64 + i1], 1);
    }
}

// ---------------------------------------------------------------------------
// Sort machinery
// ---------------------------------------------------------------------------
__global__ void zero_kernel(int* cnt) { cnt[threadIdx.x] = 0; }

// fused exclusive scans + tile->expert map
__global__ void scanfill_kernel(const int* __restrict__ cnt, int* off, int* poff,
                                int* __restrict__ tileE) {
    __shared__ int s1[2][64], s2[2][64], sp[2][65];
    int k = threadIdx.x >> 6, e = threadIdx.x & 63;
    int c  = cnt[k * 64 + e];
    int nt = (c + 7) >> 3;
    s1[k][e] = c; s2[k][e] = nt;
    __syncthreads();
    for (int d = 1; d < 64; d <<= 1) {
        int va = (e >= d) ? s1[k][e - d] : 0;
        int vb = (e >= d) ? s2[k][e - d] : 0;
        __syncthreads();
        s1[k][e] += va; s2[k][e] += vb;
        __syncthreads();
    }
    off[k * 64 + e]  = s1[k][e] - c;
    poff[k * 65 + e] = s2[k][e] - nt;
    sp[k][e] = s2[k][e] - nt;
    if (e == 63) { poff[k * 65 + 64] = s2[k][63]; sp[k][64] = s2[k][63]; }
    __syncthreads();
    for (int gq = threadIdx.x; gq < 2 * 1152; gq += 128) {
        int kk = gq / 1152, q = gq - kk * 1152;
        int ee = -1;
        if (q < sp[kk][64]) {
            int lo = 0, hi = 64;
            while (hi - lo > 1) {
                int mid = (lo + hi) >> 1;
                if (sp[kk][mid] <= q) lo = mid; else hi = mid;
            }
            ee = lo;
        }
        tileE[kk * 1152 + q] = ee;
    }
}

__global__ void scatter_kernel(const int* __restrict__ idx,
                               const int* __restrict__ off,
                               int* __restrict__ perm) {
    int k = blockIdx.x >> 6, e = blockIdx.x & 63;
    int base = off[k * 64 + e];
    __shared__ int warp_tot[8];
    __shared__ int carry;
    if (threadIdx.x == 0) carry = 0;
    __syncthreads();
    for (int t0 = 0; t0 < NTOK; t0 += 256) {
        int t = t0 + threadIdx.x;
        bool m = (idx[2 * t + k] == e);
        unsigned bal = __ballot_sync(0xffffffffu, m);
        int lane = threadIdx.x & 31, wid = threadIdx.x >> 5;
        int wpre = __popc(bal & ((1u << lane) - 1));
        if (lane == 0) warp_tot[wid] = __popc(bal);
        __syncthreads();
        int wbase = 0;
#pragma unroll
        for (int w = 0; w < 8; w++) if (w < wid) wbase += warp_tot[w];
        int tot = 0;
#pragma unroll
        for (int w = 0; w < 8; w++) tot += warp_tot[w];
        if (m) perm[k * NTOK + base + carry + wbase + wpre] = t;
        __syncthreads();
        if (threadIdx.x == 0) carry += tot;
        __syncthreads();
    }
}

// ---------------------------------------------------------------------------
// UP (tf32x3 tensor): 8 same-expert slots per CTA, 512 threads = 16 warps.
//  GEMM1: C[64, 256] = A[64,32] @ Xc[32, 256]   (n = s*32 + j), T = pk*C
//  GEMM2: Y[512, 64] = Tflat[512,32] @ B^T      (m = s*64 + o)
// smem floats (raw fp32): As[64][36] | BsT[32][72] | Xs[32][264] | Tf[512][36]
// ---------------------------------------------------------------------------
#define UA 0
#define UB 2304
#define UX 4608
#define UT 13056
#define UP_SMEM_BYTES (31488 * 4)

template <int KP>
__global__ void __launch_bounds__(512, 1)
up_gemm(const float* __restrict__ x, const float* __restrict__ A,
        const float* __restrict__ Bw, const float* __restrict__ scale,
        const float* __restrict__ bias, const float* __restrict__ prob,
        const int* __restrict__ perm, const int* __restrict__ off,
        const int* __restrict__ poff, const int* __restrict__ cnt,
        const int* __restrict__ tileE, float* __restrict__ h)
{
    extern __shared__ float sm[];
    __shared__ int sh_e, sh_t[8], sh_v[8];
    __shared__ float sh_pk[8];
    const int tid = threadIdx.x;
    const int lane = tid & 31, w = tid >> 5;
    const int g = lane >> 2, tq = lane & 3;

    if (tid == 0) {
        int b = blockIdx.x;
        int e = tileE[KP * 1152 + b];
        sh_e = e;
        if (e >= 0) {
            int n = cnt[KP * 64 + e], base = off[KP * 64 + e];
            int l0 = (b - poff[KP * 65 + e]) * 8;
            for (int s = 0; s < 8; s++) {
                int li = l0 + s;
                if (li < n) {
                    int t = perm[KP * NTOK + base + li];
                    sh_t[s] = t; sh_v[s] = 1; sh_pk[s] = prob[2 * t + KP];
                } else { sh_t[s] = 0; sh_v[s] = 0; sh_pk[s] = 0.f; }
            }
        }
    }
    __syncthreads();
    if (sh_e < 0) return;
    const int e = sh_e;

    {   // stage raw fp32: A[o][i] s36, B^T[j][p] s72, X[i][s*32+j] s264
        const float4* A4 = (const float4*)(A + e * 2048);
        const float4* B4 = (const float4*)(Bw + e * 2048);
        int o = tid >> 3, c4 = (tid & 7) * 4;
        float4 va = A4[tid], vb = B4[tid];
        *(float4*)&sm[UA + o * 36 + c4] = va;
        sm[UB + (c4 + 0) * 72 + o] = vb.x;
        sm[UB + (c4 + 1) * 72 + o] = vb.y;
        sm[UB + (c4 + 2) * 72 + o] = vb.z;
        sm[UB + (c4 + 3) * 72 + o] = vb.w;
#pragma unroll
        for (int r = 0; r < 4; r++) {
            int l = tid + 512 * r;
            int s = l >> 8, i = (l >> 3) & 31, j4 = (l & 7) * 4;
            *(float4*)&sm[UX + i * 264 + s * 32 + j4] =
                *(const float4*)&x[sh_t[s] * 1024 + i * 32 + j4];
        }
    }
    __syncthreads();

    {   // GEMM1: mw = w&3 (m-tile), nw = w>>2 (64-col n-super)
        const int mw = w & 3, nw = w >> 2;
        float acc[8][4];
#pragma unroll
        for (int nt = 0; nt < 8; nt++)
#pragma unroll
            for (int q = 0; q < 4; q++) acc[nt][q] = 0.f;
#pragma unroll
        for (int ks = 0; ks < 4; ks++) {
            tf2 a[4];
            int ro = mw * 16 + g, ci = ks * 8 + tq;
            a[0] = spl(sm[UA + ro * 36 + ci]);
            a[1] = spl(sm[UA + (ro + 8) * 36 + ci]);
            a[2] = spl(sm[UA + ro * 36 + ci + 4]);
            a[3] = spl(sm[UA + (ro + 8) * 36 + ci + 4]);
#pragma unroll
            for (int nt = 0; nt < 8; nt++) {
                tf2 b[2];
                int n = nw * 64 + nt * 8 + g;
                b[0] = spl(sm[UX + (ks * 8 + tq) * 264 + n]);
                b[1] = spl(sm[UX + (ks * 8 + tq + 4) * 264 + n]);
                mma3(acc[nt], a, b);
            }
        }
        // epilogue: T = pk * C (raw fp32) -> Tflat[(s*64+m)][j] stride 36
#pragma unroll
        for (int nt = 0; nt < 8; nt++) {
            int n0 = nw * 64 + nt * 8 + 2 * tq;
            int s = n0 >> 5, j = n0 & 31;
            float pk = sh_pk[s];
            int m0 = mw * 16 + g;
            *(float2*)&sm[UT + (s * 64 + m0) * 36 + j] =
                make_float2(acc[nt][0] * pk, acc[nt][1] * pk);
            *(float2*)&sm[UT + (s * 64 + m0 + 8) * 36 + j] =
                make_float2(acc[nt][2] * pk, acc[nt][3] * pk);
        }
    }
    __syncthreads();

    {   // GEMM2: warp w -> m-tiles {2w, 2w+1} (token s = w>>1), 8 n-tiles in 2 chunks
        const int s = w >> 1;
        const float s0 = scale[0];
        float* hrow = h + sh_t[s] * 4096;
#pragma unroll 1
        for (int nc = 0; nc < 2; nc++) {
            float acc[2][4][4];
#pragma unroll
            for (int mm = 0; mm < 2; mm++)
#pragma unroll
                for (int nt = 0; nt < 4; nt++)
#pragma unroll
                    for (int q = 0; q < 4; q++) acc[mm][nt][q] = 0.f;
#pragma unroll
            for (int ks = 0; ks < 4; ks++) {
                tf2 a[2][4];
#pragma unroll
                for (int mm = 0; mm < 2; mm++) {
                    int m0 = (2 * w + mm) * 16 + g, cj = ks * 8 + tq;
                    a[mm][0] = spl(sm[UT + m0 * 36 + cj]);
                    a[mm][1] = spl(sm[UT + (m0 + 8) * 36 + cj]);
                    a[mm][2] = spl(sm[UT + m0 * 36 + cj + 4]);
                    a[mm][3] = spl(sm[UT + (m0 + 8) * 36 + cj + 4]);
                }
#pragma unroll
                for (int nt = 0; nt < 4; nt++) {
                    tf2 b[2];
                    int p = (nc * 4 + nt) * 8 + g;
                    b[0] = spl(sm[UB + (ks * 8 + tq) * 72 + p]);
                    b[1] = spl(sm[UB + (ks * 8 + tq + 4) * 72 + p]);
                    mma3(acc[0][nt], a[0], b);
                    mma3(acc[1][nt], a[1], b);
                }
            }
            if (sh_v[s]) {
#pragma unroll
                for (int mm = 0; mm < 2; mm++) {
                    int m0 = (2 * w + mm) * 16 + g;
#pragma unroll
                    for (int hh = 0; hh < 2; hh++) {
                        int o = (m0 + 8 * hh) & 63;
#pragma unroll
                        for (int nt = 0; nt < 4; nt++) {
                            int p = (nc * 4 + nt) * 8 + 2 * tq;
                            float c0 = acc[mm][nt][2 * hh], c1 = acc[mm][nt][2 * hh + 1];
                            float* dst = hrow + o * 64 + p;
                            if (KP == 0) {
                                *(float2*)dst = make_float2(c0, c1);
                            } else {
                                float2 cur = *(const float2*)dst;
                                float2 bs = *(const float2*)&bias[o * 64 + p];
                                float y0 = (cur.x + c0) * s0 + bs.x;
                                float y1 = (cur.y + c1) * s0 + bs.y;
                                *(float2*)dst = make_float2(gelu_f(y0), gelu_f(y1));
                            }
                        }
                    }
                }
            }
        }
    }
}

// ---------------------------------------------------------------------------
// DOWN (tf32x3 tensor): 8 same-expert slots per CTA, 512 threads.
//  GEMM1: C[32, 512] = A[32,64] @ Xc[64, 512]  (n = s*64 + j), T = pk*C
//  GEMM2: Y[256, 32] = Tflat[256,64] @ B^T     (m = s*32 + o)
// X streamed in 4 slabs of 16 rows with register prefetch.
// smem floats (raw fp32): As[32][68] | BsT[64][40] | Xs[16][520] | Tf[256][68]
// ---------------------------------------------------------------------------
#define DA 0
#define DB 2176
#define DX 4736
#define DT 13056
#define DN_SMEM_BYTES (30464 * 4)

template <int KP>
__global__ void __launch_bounds__(512, 1)
down_gemm(const float* __restrict__ hbuf, const float* __restrict__ A,
          const float* __restrict__ Bw, const float* __restrict__ scale,
          const float* __restrict__ bias, const float* __restrict__ prob,
          const int* __restrict__ perm, const int* __restrict__ off,
          const int* __restrict__ poff, const int* __restrict__ cnt,
          const int* __restrict__ tileE, float* __restrict__ out)
{
    extern __shared__ float sm[];
    __shared__ int sh_e, sh_t[8], sh_v[8];
    __shared__ float sh_pk[8];
    const int tid = threadIdx.x;
    const int lane = tid & 31, w = tid >> 5;
    const int g = lane >> 2, tq = lane & 3;

    if (tid == 0) {
        int b = blockIdx.x;
        int e = tileE[KP * 1152 + b];
        sh_e = e;
        if (e >= 0) {
            int n = cnt[KP * 64 + e], base = off[KP * 64 + e];
            int l0 = (b - poff[KP * 65 + e]) * 8;
            for (int s = 0; s < 8; s++) {
                int li = l0 + s;
                if (li < n) {
                    int t = perm[KP * NTOK + base + li];
                    sh_t[s] = t; sh_v[s] = 1; sh_pk[s] = prob[2 * t + KP];
                } else { sh_t[s] = 0; sh_v[s] = 0; sh_pk[s] = 0.f; }
            }
        }
    }
    __syncthreads();
    if (sh_e < 0) return;
    const int e = sh_e;

    {   // stage raw fp32: A[o][i] s68, B^T[j][p] s40
        const float4* A4 = (const float4*)(A + e * 2048);
        const float4* B4 = (const float4*)(Bw + e * 2048);
        int o = tid >> 4, c4 = (tid & 15) * 4;
        float4 va = A4[tid], vb = B4[tid];
        *(float4*)&sm[DA + o * 68 + c4] = va;
        sm[DB + (c4 + 0) * 40 + o] = vb.x;
        sm[DB + (c4 + 1) * 40 + o] = vb.y;
        sm[DB + (c4 + 2) * 40 + o] = vb.z;
        sm[DB + (c4 + 3) * 40 + o] = vb.w;
    }

    {   // GEMM1: warp w owns n-super [32w, 32w+32), both m-tiles; X slab-streamed
        const int xs_ = (tid >> 4) & 7, xj4 = (tid & 15) * 4;
        float acc[2][4][4];
#pragma unroll
        for (int mm = 0; mm < 2; mm++)
#pragma unroll
            for (int nt = 0; nt < 4; nt++)
#pragma unroll
                for (int q = 0; q < 4; q++) acc[mm][nt][q] = 0.f;

        float4 pre[4];
#pragma unroll
        for (int r = 0; r < 4; r++) {
            int i = ((tid + 512 * r) >> 7) & 15;
            pre[r] = *(const float4*)&hbuf[sh_t[xs_] * 4096 + i * 64 + xj4];
        }

#pragma unroll 1
        for (int slab = 0; slab < 4; slab++) {
            __syncthreads();
#pragma unroll
            for (int r = 0; r < 4; r++) {
                int i = ((tid + 512 * r) >> 7) & 15;
                *(float4*)&sm[DX + i * 520 + xs_ * 64 + xj4] = pre[r];
            }
            __syncthreads();
            if (slab < 3) {
#pragma unroll
                for (int r = 0; r < 4; r++) {
                    int i = ((tid + 512 * r) >> 7) & 15;
                    pre[r] = *(const float4*)&hbuf[sh_t[xs_] * 4096 +
                                                   ((slab + 1) * 16 + i) * 64 + xj4];
                }
            }
#pragma unroll
            for (int kl = 0; kl < 2; kl++) {
                int gi = slab * 16 + kl * 8;
                tf2 a[2][4];
#pragma unroll
                for (int mm = 0; mm < 2; mm++) {
                    int ro = mm * 16 + g;
                    a[mm][0] = spl(sm[DA + ro * 68 + gi + tq]);
                    a[mm][1] = spl(sm[DA + (ro + 8) * 68 + gi + tq]);
                    a[mm][2] = spl(sm[DA + ro * 68 + gi + tq + 4]);
                    a[mm][3] = spl(sm[DA + (ro + 8) * 68 + gi + tq + 4]);
                }
#pragma unroll
                for (int nt = 0; nt < 4; nt++) {
                    tf2 b[2];
                    int n = w * 32 + nt * 8 + g;
                    b[0] = spl(sm[DX + (kl * 8 + tq) * 520 + n]);
                    b[1] = spl(sm[DX + (kl * 8 + tq + 4) * 520 + n]);
                    mma3(acc[0][nt], a[0], b);
                    mma3(acc[1][nt], a[1], b);
                }
            }
        }
        // epilogue: T = pk * C (raw) -> Tflat[(s*32+o)][j] stride 68
        const int s = w >> 1;
        const float pk = sh_pk[s];
#pragma unroll
        for (int mm = 0; mm < 2; mm++) {
            int o0 = mm * 16 + g;
#pragma unroll
            for (int nt = 0; nt < 4; nt++) {
                int n0 = w * 32 + nt * 8 + 2 * tq;
                int j = n0 & 63;
                *(float2*)&sm[DT + (s * 32 + o0) * 68 + j] =
                    make_float2(acc[mm][nt][0] * pk, acc[mm][nt][1] * pk);
                *(float2*)&sm[DT + (s * 32 + o0 + 8) * 68 + j] =
                    make_float2(acc[mm][nt][2] * pk, acc[mm][nt][3] * pk);
            }
        }
    }
    __syncthreads();

    {   // GEMM2: warp w owns m-tile w (token s = w>>1), 4 n-tiles, K=64
        float acc[4][4];
#pragma unroll
        for (int nt = 0; nt < 4; nt++)
#pragma unroll
            for (int q = 0; q < 4; q++) acc[nt][q] = 0.f;
#pragma unroll
        for (int ks = 0; ks < 8; ks++) {
            tf2 a[4];
            int m0 = w * 16 + g, cj = ks * 8 + tq;
            a[0] = spl(sm[DT + m0 * 68 + cj]);
            a[1] = spl(sm[DT + (m0 + 8) * 68 + cj]);
            a[2] = spl(sm[DT + m0 * 68 + cj + 4]);
            a[3] = spl(sm[DT + (m0 + 8) * 68 + cj + 4]);
#pragma unroll
            for (int nt = 0; nt < 4; nt++) {
                tf2 b[2];
                int p = nt * 8 + g;
                b[0] = spl(sm[DB + (ks * 8 + tq) * 40 + p]);
                b[1] = spl(sm[DB + (ks * 8 + tq + 4) * 40 + p]);
                mma3(acc[nt], a, b);
            }
        }
        const int s = w >> 1;
        if (sh_v[s]) {
            const float s0 = scale[0];
            float* orow = out + sh_t[s] * 1024;
            int m0 = w * 16 + g;
#pragma unroll
            for (int hh = 0; hh < 2; hh++) {
                int o = (m0 + 8 * hh) & 31;
#pragma unroll
                for (int nt = 0; nt < 4; nt++) {
                    int p = nt * 8 + 2 * tq;
                    float c0 = acc[nt][2 * hh], c1 = acc[nt][2 * hh + 1];
                    float* dst = orow + o * 32 + p;
                    if (KP == 0) {
                        *(float2*)dst = make_float2(c0, c1);
                    } else {
                        float2 cur = *(const float2*)dst;
                        float2 bs = *(const float2*)&bias[o * 32 + p];
                        *(float2*)dst = make_float2((cur.x + c0) * s0 + bs.x,
                                                    (cur.y + c1) * s0 + bs.y);
                    }
                }
            }
        }
    }
}

// ---------------------------------------------------------------------------
extern "C" void kernel_launch(void* const* d_in, const int* in_sizes, int n_in,
                              void* d_out, int out_size)
{
    const float* x          = (const float*)d_in[0];
    const float* W_up       = (const float*)d_in[1];
    const float* A_up       = (const float*)d_in[2];
    const float* B_up       = (const float*)d_in[3];
    const float* scale_up   = (const float*)d_in[4];
    const float* bias_up    = (const float*)d_in[5];
    const float* W_down     = (const float*)d_in[6];
    const float* A_down     = (const float*)d_in[7];
    const float* B_down     = (const float*)d_in[8];
    const float* scale_down = (const float*)d_in[9];
    const float* bias_down  = (const float*)d_in[10];
    float* out = (float*)d_out;

    float *h, *pu, *pd, *whu, *wlu, *whd, *wld;
    int *iu, *idn, *cnt, *off, *poff, *tileE, *perm;
    cudaGetSymbolAddress((void**)&h,     g_h);
    cudaGetSymbolAddress((void**)&iu,    g_idx_up);
    cudaGetSymbolAddress((void**)&pu,    g_prob_up);
    cudaGetSymbolAddress((void**)&idn,   g_idx_dn);
    cudaGetSymbolAddress((void**)&pd,    g_prob_dn);
    cudaGetSymbolAddress((void**)&cnt,   g_cnt);
    cudaGetSymbolAddress((void**)&off,   g_off);
    cudaGetSymbolAddress((void**)&poff,  g_poff);
    cudaGetSymbolAddress((void**)&tileE, g_tileE);
    cudaGetSymbolAddress((void**)&perm,  g_perm);
    cudaGetSymbolAddress((void**)&whu,   g_WhU);
    cudaGetSymbolAddress((void**)&wlu,   g_WlU);
    cudaGetSymbolAddress((void**)&whd,   g_WhD);
    cudaGetSymbolAddress((void**)&wld,   g_WlD);

    cudaFuncSetAttribute(router_kernel<1024>, cudaFuncAttributeMaxDynamicSharedMemorySize, R_SMEM_BYTES);
    cudaFuncSetAttribute(router_kernel<4096>, cudaFuncAttributeMaxDynamicSharedMemorySize, R_SMEM_BYTES);
    cudaFuncSetAttribute(up_gemm<0>,   cudaFuncAttributeMaxDynamicSharedMemorySize, UP_SMEM_BYTES);
    cudaFuncSetAttribute(up_gemm<1>,   cudaFuncAttributeMaxDynamicSharedMemorySize, UP_SMEM_BYTES);
    cudaFuncSetAttribute(down_gemm<0>, cudaFuncAttributeMaxDynamicSharedMemorySize, DN_SMEM_BYTES);
    cudaFuncSetAttribute(down_gemm<1>, cudaFuncAttributeMaxDynamicSharedMemorySize, DN_SMEM_BYTES);

    const int GRID = 1088;

    // W pre-splits (independent of token data)
    split_w<<<(64 * 1024 + 255) / 256, 256>>>(W_up,   whu, wlu, 64 * 1024);
    split_w<<<(64 * 4096 + 255) / 256, 256>>>(W_down, whd, wld, 64 * 4096);

    // up path
    zero_kernel<<<1, 128>>>(cnt);
    router_kernel<1024><<<NTOK / 64, 256, R_SMEM_BYTES>>>(x, whu, wlu, iu, pu, cnt);
    scanfill_kernel<<<1, 128>>>(cnt, off, poff, tileE);
    scatter_kernel<<<128, 256>>>(iu, off, perm);
    up_gemm<0><<<GRID, 512, UP_SMEM_BYTES>>>(x, A_up, B_up, scale_up, bias_up,
                                             pu, perm, off, poff, cnt, tileE, h);
    up_gemm<1><<<GRID, 512, UP_SMEM_BYTES>>>(x, A_up, B_up, scale_up, bias_up,
                                             pu, perm, off, poff, cnt, tileE, h);

    // down path
    zero_kernel<<<1, 128>>>(cnt);
    router_kernel<4096><<<NTOK / 64, 256, R_SMEM_BYTES>>>(h, whd, wld, idn, pd, cnt);
    scanfill_kernel<<<1, 128>>>(cnt, off, poff, tileE);
    scatter_kernel<<<128, 256>>>(idn, off, perm);
    down_gemm<0><<<GRID, 512, DN_SMEM_BYTES>>>(h, A_down, B_down, scale_down, bias_down,
                                               pd, perm, off, poff, cnt, tileE, out);
    down_gemm<1><<<GRID, 512, DN_SMEM_BYTES>>>(h, A_down, B_down, scale_down, bias_down,
                                               pd, perm, off, poff, cnt, tileE, out);
}